// round 1
// baseline (speedup 1.0000x reference)
#include <cuda_runtime.h>
#include <math.h>

#define T     4096
#define DIN   1024
#define DOUT  1024
#define NE    8
#define HID   4096
#define BM    128
#define BN    128
#define BK    8
#define MT_MAX (T / BM)   // 32 worst-case M tiles per expert

// ---------------- device scratch (static: no allocation allowed) ----------------
__device__ int   g_count[NE];
__device__ int   g_offset[NE];
__device__ int   g_tokens[NE * T];
__device__ int   g_tok_e[T * 2];
__device__ int   g_tok_pos[T * 2];
__device__ float g_tok_w[T * 2];
__device__ float g_H[(size_t)T * 2 * HID];    // 8192 x 4096 fp32 = 128 MiB
__device__ float g_O[(size_t)T * 2 * DOUT];   // 8192 x 1024 fp32 = 32 MiB
__device__ float g_wdummy[T * NE];            // fallback if out buffer lacks weights region

// ---------------- kernel 0: zero per-expert counters (must run every replay) ----
__global__ void zero_counts_kernel() {
    if (threadIdx.x < NE) g_count[threadIdx.x] = 0;
}

// ---------------- kernel 1: noisy gating + top-2 + bucket assignment ------------
__global__ void gating_kernel(const float* __restrict__ x,
                              const float* __restrict__ noise,
                              const float* __restrict__ gate_w,
                              const float* __restrict__ gate_b,
                              const float* __restrict__ noise_w,
                              const float* __restrict__ noise_b,
                              float* __restrict__ w_out) {
    int warp = blockIdx.x * (blockDim.x >> 5) + (threadIdx.x >> 5);
    int lane = threadIdx.x & 31;
    if (warp >= T) return;
    const float* xr = x + (size_t)warp * DIN;

    float ag[NE], an[NE];
#pragma unroll
    for (int e = 0; e < NE; e++) { ag[e] = 0.f; an[e] = 0.f; }

    for (int ii = 0; ii < DIN / 32; ii++) {
        int i = ii * 32 + lane;
        float xv = xr[i];
        float4 g0 = *(const float4*)(gate_w + (size_t)i * NE);
        float4 g1 = *(const float4*)(gate_w + (size_t)i * NE + 4);
        float4 n0 = *(const float4*)(noise_w + (size_t)i * NE);
        float4 n1 = *(const float4*)(noise_w + (size_t)i * NE + 4);
        ag[0] = fmaf(xv, g0.x, ag[0]); ag[1] = fmaf(xv, g0.y, ag[1]);
        ag[2] = fmaf(xv, g0.z, ag[2]); ag[3] = fmaf(xv, g0.w, ag[3]);
        ag[4] = fmaf(xv, g1.x, ag[4]); ag[5] = fmaf(xv, g1.y, ag[5]);
        ag[6] = fmaf(xv, g1.z, ag[6]); ag[7] = fmaf(xv, g1.w, ag[7]);
        an[0] = fmaf(xv, n0.x, an[0]); an[1] = fmaf(xv, n0.y, an[1]);
        an[2] = fmaf(xv, n0.z, an[2]); an[3] = fmaf(xv, n0.w, an[3]);
        an[4] = fmaf(xv, n1.x, an[4]); an[5] = fmaf(xv, n1.y, an[5]);
        an[6] = fmaf(xv, n1.z, an[6]); an[7] = fmaf(xv, n1.w, an[7]);
    }
#pragma unroll
    for (int e = 0; e < NE; e++) {
#pragma unroll
        for (int o = 16; o > 0; o >>= 1) {
            ag[e] += __shfl_xor_sync(0xffffffffu, ag[e], o);
            an[e] += __shfl_xor_sync(0xffffffffu, an[e], o);
        }
    }

    if (lane == 0) {
        float l[NE];
#pragma unroll
        for (int e = 0; e < NE; e++) {
            float z = an[e] + noise_b[e];
            float sp = (z > 20.f) ? z : log1pf(expf(z));
            l[e] = ag[e] + gate_b[e] + noise[(size_t)warp * NE + e] * sp;
        }
        // top-2 (E=8)
        int i0 = 0; float v0 = l[0];
#pragma unroll
        for (int e = 1; e < NE; e++) if (l[e] > v0) { v0 = l[e]; i0 = e; }
        int i1 = -1; float v1 = -INFINITY;
#pragma unroll
        for (int e = 0; e < NE; e++) if (e != i0 && l[e] > v1) { v1 = l[e]; i1 = e; }
        // softmax over the two selected logits
        float eb = expf(v1 - v0);
        float w0 = 1.f / (1.f + eb);
        float w1 = eb / (1.f + eb);

        float wrow[NE];
#pragma unroll
        for (int e = 0; e < NE; e++) wrow[e] = 0.f;
        wrow[i0] = w0; wrow[i1] = w1;
#pragma unroll
        for (int e = 0; e < NE; e++) w_out[(size_t)warp * NE + e] = wrow[e];

        int p0 = atomicAdd(&g_count[i0], 1);
        int p1 = atomicAdd(&g_count[i1], 1);
        g_tokens[i0 * T + p0] = warp;
        g_tokens[i1 * T + p1] = warp;
        g_tok_e[2 * warp]     = i0; g_tok_pos[2 * warp]     = p0; g_tok_w[2 * warp]     = w0;
        g_tok_e[2 * warp + 1] = i1; g_tok_pos[2 * warp + 1] = p1; g_tok_w[2 * warp + 1] = w1;
    }
}

// ---------------- kernel 2: exclusive prefix offsets over 8 counters ------------
__global__ void offsets_kernel() {
    if (threadIdx.x == 0) {
        int s = 0;
        for (int e = 0; e < NE; e++) { g_offset[e] = s; s += g_count[e]; }
    }
}

// ---------------- kernels 3/4: per-expert tiled SGEMM ---------------------------
// GATHER=true : C=g_H, A=x gathered by token list, relu(acc+b1)
// GATHER=false: C=g_O, A=g_H contiguous expert rows, acc+b2
template <int KD, int ND, bool GATHER, bool RELU>
__global__ __launch_bounds__(256, 2)
void expert_gemm_kernel(const float* __restrict__ X,
                        const float* __restrict__ B,
                        const float* __restrict__ bias) {
    int e  = blockIdx.x / MT_MAX;
    int mt = blockIdx.x % MT_MAX;
    int cnt = g_count[e];
    int m0 = mt * BM;
    if (m0 >= cnt) return;
    int n0 = blockIdx.y * BN;
    int base = g_offset[e];

    __shared__ float As[BK][BM];
    __shared__ float Bs[BK][BN];
    __shared__ int   toks[BM];

    int tid = threadIdx.x;
    if (GATHER) {
        if (tid < BM) {
            int rr = m0 + tid;
            toks[tid] = (rr < cnt) ? g_tokens[e * T + rr] : -1;
        }
        __syncthreads();
    }

    int arow = tid >> 1, ahalf = tid & 1;
    const float* aptr;
    bool avalid;
    if (GATHER) {
        int tok = toks[arow];
        avalid = (tok >= 0);
        aptr = X + (size_t)(avalid ? tok : 0) * KD + ahalf * 4;
    } else {
        avalid = (m0 + arow < cnt);
        int rr = avalid ? (base + m0 + arow) : 0;
        aptr = g_H + (size_t)rr * KD + ahalf * 4;
    }

    const float* Be = B + (size_t)e * KD * ND;
    const float* be = bias + (size_t)e * ND;
    float* C = GATHER ? g_H : g_O;

    int bkk = tid >> 5;
    int bcol = (tid & 31) << 2;
    int tx = tid & 15, ty = tid >> 4;

    float acc[8][8];
#pragma unroll
    for (int i = 0; i < 8; i++)
#pragma unroll
        for (int j = 0; j < 8; j++) acc[i][j] = 0.f;

    for (int k0 = 0; k0 < KD; k0 += BK) {
        float4 av = avalid ? *(const float4*)(aptr + k0) : make_float4(0.f, 0.f, 0.f, 0.f);
        float4 bv = *(const float4*)(Be + (size_t)(k0 + bkk) * ND + n0 + bcol);
        __syncthreads();
        As[ahalf * 4 + 0][arow] = av.x;
        As[ahalf * 4 + 1][arow] = av.y;
        As[ahalf * 4 + 2][arow] = av.z;
        As[ahalf * 4 + 3][arow] = av.w;
        *(float4*)&Bs[bkk][bcol] = bv;
        __syncthreads();
#pragma unroll
        for (int kk = 0; kk < BK; kk++) {
            float a[8], b[8];
            *(float4*)&a[0] = *(const float4*)&As[kk][ty * 8];
            *(float4*)&a[4] = *(const float4*)&As[kk][ty * 8 + 4];
            *(float4*)&b[0] = *(const float4*)&Bs[kk][tx * 8];
            *(float4*)&b[4] = *(const float4*)&Bs[kk][tx * 8 + 4];
#pragma unroll
            for (int i = 0; i < 8; i++)
#pragma unroll
                for (int j = 0; j < 8; j++)
                    acc[i][j] = fmaf(a[i], b[j], acc[i][j]);
        }
    }

    int c0 = n0 + tx * 8;
#pragma unroll
    for (int i = 0; i < 8; i++) {
        int r = ty * 8 + i;
        if (m0 + r < cnt) {
            float* dst = C + (size_t)(base + m0 + r) * ND + c0;
            float4 v0, v1;
            v0.x = acc[i][0] + be[c0 + 0]; v0.y = acc[i][1] + be[c0 + 1];
            v0.z = acc[i][2] + be[c0 + 2]; v0.w = acc[i][3] + be[c0 + 3];
            v1.x = acc[i][4] + be[c0 + 4]; v1.y = acc[i][5] + be[c0 + 5];
            v1.z = acc[i][6] + be[c0 + 6]; v1.w = acc[i][7] + be[c0 + 7];
            if (RELU) {
                v0.x = fmaxf(v0.x, 0.f); v0.y = fmaxf(v0.y, 0.f);
                v0.z = fmaxf(v0.z, 0.f); v0.w = fmaxf(v0.w, 0.f);
                v1.x = fmaxf(v1.x, 0.f); v1.y = fmaxf(v1.y, 0.f);
                v1.z = fmaxf(v1.z, 0.f); v1.w = fmaxf(v1.w, 0.f);
            }
            *(float4*)dst = v0;
            *(float4*)(dst + 4) = v1;
        }
    }
}

// ---------------- kernel 5: weighted combine of the two expert rows -------------
__global__ void combine_kernel(float* __restrict__ out) {
    int t = blockIdx.x;
    int e0 = g_tok_e[2 * t],     e1 = g_tok_e[2 * t + 1];
    int r0 = g_offset[e0] + g_tok_pos[2 * t];
    int r1 = g_offset[e1] + g_tok_pos[2 * t + 1];
    float w0 = g_tok_w[2 * t],   w1 = g_tok_w[2 * t + 1];
    const float4* a = (const float4*)(g_O + (size_t)r0 * DOUT);
    const float4* b = (const float4*)(g_O + (size_t)r1 * DOUT);
    float4* o = (float4*)(out + (size_t)t * DOUT);
    for (int i = threadIdx.x; i < DOUT / 4; i += blockDim.x) {
        float4 av = a[i], bv = b[i];
        float4 r;
        r.x = w0 * av.x + w1 * bv.x;
        r.y = w0 * av.y + w1 * bv.y;
        r.z = w0 * av.z + w1 * bv.z;
        r.w = w0 * av.w + w1 * bv.w;
        o[i] = r;
    }
}

// ---------------- launch -------------------------------------------------------
extern "C" void kernel_launch(void* const* d_in, const int* in_sizes, int n_in,
                              void* d_out, int out_size) {
    const float* x       = (const float*)d_in[0];
    const float* noise   = (const float*)d_in[1];
    const float* gate_w  = (const float*)d_in[2];
    const float* gate_b  = (const float*)d_in[3];
    const float* noise_w = (const float*)d_in[4];
    const float* noise_b = (const float*)d_in[5];
    const float* w1      = (const float*)d_in[6];
    const float* b1      = (const float*)d_in[7];
    const float* w2      = (const float*)d_in[8];
    const float* b2      = (const float*)d_in[9];
    float* out = (float*)d_out;

    // weights output lives after x_out if the buffer has room for it
    float* w_out;
    if (out_size >= T * DOUT + T * NE) {
        w_out = out + (size_t)T * DOUT;
    } else {
        cudaGetSymbolAddress((void**)&w_out, g_wdummy);
    }

    zero_counts_kernel<<<1, 32>>>();
    gating_kernel<<<T / 4, 128>>>(x, noise, gate_w, gate_b, noise_w, noise_b, w_out);
    offsets_kernel<<<1, 32>>>();
    expert_gemm_kernel<DIN, HID, true,  true ><<<dim3(NE * MT_MAX, HID / BN),  256>>>(x, w1, b1);
    expert_gemm_kernel<HID, DOUT, false, false><<<dim3(NE * MT_MAX, DOUT / BN), 256>>>(nullptr, w2, b2);
    combine_kernel<<<T, 256>>>(out);
}

// round 3
// speedup vs baseline: 2.0435x; 2.0435x over previous
#include <cuda_runtime.h>
#include <cuda_bf16.h>
#include <math.h>
#include <stdint.h>

#define T      4096
#define DIN    1024
#define DOUT   1024
#define NE     8
#define HID    4096
#define BM     128
#define BN     128
#define BK     32
#define MT_MAX 32
#define NSTAGE 4
#define ROWB   80          // smem row stride (64B data + 16B skew)
#define MAT_BYTES (128 * ROWB)       // 10240
#define STG_BYTES (4 * MAT_BYTES)    // 40960
#define SMEM_TOT  (1024 + NSTAGE * STG_BYTES)  // 164864

// ---------------------------------------------------------------- helpers
__device__ __forceinline__ uint32_t smem_to_u32(const void* p) {
    uint32_t a;
    asm("{ .reg .u64 t; cvta.to.shared.u64 t, %1; cvt.u32.u64 %0, t; }" : "=r"(a) : "l"(p));
    return a;
}
__device__ __forceinline__ void ldmx4(uint32_t* r, uint32_t addr) {
    asm volatile("ldmatrix.sync.aligned.m8n8.x4.shared.b16 {%0,%1,%2,%3}, [%4];"
                 : "=r"(r[0]), "=r"(r[1]), "=r"(r[2]), "=r"(r[3]) : "r"(addr));
}
__device__ __forceinline__ void mma_bf16(float* c, const uint32_t* a, uint32_t b0, uint32_t b1) {
    asm volatile("mma.sync.aligned.m16n8k16.row.col.f32.bf16.bf16.f32 "
                 "{%0,%1,%2,%3}, {%4,%5,%6,%7}, {%8,%9}, {%0,%1,%2,%3};"
                 : "+f"(c[0]), "+f"(c[1]), "+f"(c[2]), "+f"(c[3])
                 : "r"(a[0]), "r"(a[1]), "r"(a[2]), "r"(a[3]), "r"(b0), "r"(b1));
}
__device__ __forceinline__ void cp_async16(uint32_t dst, const void* src, uint32_t sz) {
    asm volatile("cp.async.cg.shared.global [%0], [%1], 16, %2;"
                 :: "r"(dst), "l"(src), "r"(sz));
}
#define CP_COMMIT() asm volatile("cp.async.commit_group;")
#define CP_WAIT(n)  asm volatile("cp.async.wait_group %0;" :: "n"(n))

// ---------------------------------------------------------------- device state
__device__ int   g_count[NE];
__device__ int   g_offset[NE];
__device__ int   g_tokens[NE * T];
__device__ int   g_tok_e[T * 2];
__device__ int   g_tok_pos[T * 2];
__device__ float g_tok_w[T * 2];
__device__ __align__(16) __nv_bfloat16 g_xhi[(size_t)T * DIN];
__device__ __align__(16) __nv_bfloat16 g_xlo[(size_t)T * DIN];
__device__ __align__(16) __nv_bfloat16 g_w1hi[(size_t)NE * HID * DIN];  // [e][n(H)][k(DIN)]
__device__ __align__(16) __nv_bfloat16 g_w1lo[(size_t)NE * HID * DIN];
__device__ __align__(16) __nv_bfloat16 g_w2hi[(size_t)NE * DOUT * HID]; // [e][n(O)][k(H)]
__device__ __align__(16) __nv_bfloat16 g_w2lo[(size_t)NE * DOUT * HID];
__device__ __align__(16) __nv_bfloat16 g_hhi[(size_t)T * 2 * HID];
__device__ __align__(16) __nv_bfloat16 g_hlo[(size_t)T * 2 * HID];
__device__ __align__(16) float g_O[(size_t)T * 2 * DOUT];
__device__ float g_wdummy[T * NE];

// ---------------------------------------------------------------- small kernels
__global__ void zero_counts_kernel() {
    if (threadIdx.x < NE) g_count[threadIdx.x] = 0;
}

__global__ void split_x_kernel(const float* __restrict__ x) {
    int i = blockIdx.x * blockDim.x + threadIdx.x;
    if (i >= T * DIN / 4) return;
    float4 v = ((const float4*)x)[i];
    union { unsigned short u[4]; uint2 p; } ph, pl;
    float vv[4] = {v.x, v.y, v.z, v.w};
#pragma unroll
    for (int j = 0; j < 4; j++) {
        __nv_bfloat16 h = __float2bfloat16(vv[j]);
        __nv_bfloat16 l = __float2bfloat16(vv[j] - __bfloat162float(h));
        ph.u[j] = *(unsigned short*)&h;
        pl.u[j] = *(unsigned short*)&l;
    }
    ((uint2*)g_xhi)[i] = ph.p;
    ((uint2*)g_xlo)[i] = pl.p;
}

// W [e][Kd][Nd] row-major -> hi/lo [e][Nd][Kd] (K-major, transposed)
template <int WHICH>
__global__ void tsplit_kernel(const float* __restrict__ W) {
    constexpr int Kd = (WHICH == 1) ? DIN : HID;
    constexpr int Nd = (WHICH == 1) ? HID : DOUT;
    __nv_bfloat16* hi = (WHICH == 1) ? g_w1hi : g_w2hi;
    __nv_bfloat16* lo = (WHICH == 1) ? g_w1lo : g_w2lo;
    int e = blockIdx.z;
    int n0 = blockIdx.x * 32, k0 = blockIdx.y * 32;
    __shared__ float tile[32][33];
    const float* We = W + (size_t)e * Kd * Nd;
    int tx = threadIdx.x, ty = threadIdx.y;
#pragma unroll
    for (int r = ty; r < 32; r += 8)
        tile[r][tx] = We[(size_t)(k0 + r) * Nd + n0 + tx];
    __syncthreads();
    size_t ob = (size_t)e * Nd * Kd;
#pragma unroll
    for (int r = ty; r < 32; r += 8) {
        int n = n0 + r, k = k0 + tx;
        float v = tile[tx][r];
        __nv_bfloat16 hv = __float2bfloat16(v);
        hi[ob + (size_t)n * Kd + k] = hv;
        lo[ob + (size_t)n * Kd + k] = __float2bfloat16(v - __bfloat162float(hv));
    }
}

__global__ void gating_kernel(const float* __restrict__ x,
                              const float* __restrict__ noise,
                              const float* __restrict__ gate_w,
                              const float* __restrict__ gate_b,
                              const float* __restrict__ noise_w,
                              const float* __restrict__ noise_b,
                              float* __restrict__ w_out) {
    int warp = blockIdx.x * (blockDim.x >> 5) + (threadIdx.x >> 5);
    int lane = threadIdx.x & 31;
    if (warp >= T) return;
    const float* xr = x + (size_t)warp * DIN;

    float ag[NE], an[NE];
#pragma unroll
    for (int e = 0; e < NE; e++) { ag[e] = 0.f; an[e] = 0.f; }
    for (int ii = 0; ii < DIN / 32; ii++) {
        int i = ii * 32 + lane;
        float xv = xr[i];
        float4 g0 = *(const float4*)(gate_w + (size_t)i * NE);
        float4 g1 = *(const float4*)(gate_w + (size_t)i * NE + 4);
        float4 n0 = *(const float4*)(noise_w + (size_t)i * NE);
        float4 n1 = *(const float4*)(noise_w + (size_t)i * NE + 4);
        ag[0] = fmaf(xv, g0.x, ag[0]); ag[1] = fmaf(xv, g0.y, ag[1]);
        ag[2] = fmaf(xv, g0.z, ag[2]); ag[3] = fmaf(xv, g0.w, ag[3]);
        ag[4] = fmaf(xv, g1.x, ag[4]); ag[5] = fmaf(xv, g1.y, ag[5]);
        ag[6] = fmaf(xv, g1.z, ag[6]); ag[7] = fmaf(xv, g1.w, ag[7]);
        an[0] = fmaf(xv, n0.x, an[0]); an[1] = fmaf(xv, n0.y, an[1]);
        an[2] = fmaf(xv, n0.z, an[2]); an[3] = fmaf(xv, n0.w, an[3]);
        an[4] = fmaf(xv, n1.x, an[4]); an[5] = fmaf(xv, n1.y, an[5]);
        an[6] = fmaf(xv, n1.z, an[6]); an[7] = fmaf(xv, n1.w, an[7]);
    }
#pragma unroll
    for (int e = 0; e < NE; e++) {
#pragma unroll
        for (int o = 16; o > 0; o >>= 1) {
            ag[e] += __shfl_xor_sync(0xffffffffu, ag[e], o);
            an[e] += __shfl_xor_sync(0xffffffffu, an[e], o);
        }
    }
    if (lane == 0) {
        float l[NE];
#pragma unroll
        for (int e = 0; e < NE; e++) {
            float z = an[e] + noise_b[e];
            float sp = (z > 20.f) ? z : log1pf(expf(z));
            l[e] = ag[e] + gate_b[e] + noise[(size_t)warp * NE + e] * sp;
        }
        int i0 = 0; float v0 = l[0];
#pragma unroll
        for (int e = 1; e < NE; e++) if (l[e] > v0) { v0 = l[e]; i0 = e; }
        int i1 = -1; float v1 = -INFINITY;
#pragma unroll
        for (int e = 0; e < NE; e++) if (e != i0 && l[e] > v1) { v1 = l[e]; i1 = e; }
        float eb = expf(v1 - v0);
        float w0 = 1.f / (1.f + eb);
        float w1 = eb / (1.f + eb);
        float wrow[NE];
#pragma unroll
        for (int e = 0; e < NE; e++) wrow[e] = 0.f;
        wrow[i0] = w0; wrow[i1] = w1;
#pragma unroll
        for (int e = 0; e < NE; e++) w_out[(size_t)warp * NE + e] = wrow[e];
        int p0 = atomicAdd(&g_count[i0], 1);
        int p1 = atomicAdd(&g_count[i1], 1);
        g_tokens[i0 * T + p0] = warp;
        g_tokens[i1 * T + p1] = warp;
        g_tok_e[2 * warp]     = i0; g_tok_pos[2 * warp]     = p0; g_tok_w[2 * warp]     = w0;
        g_tok_e[2 * warp + 1] = i1; g_tok_pos[2 * warp + 1] = p1; g_tok_w[2 * warp + 1] = w1;
    }
}

__global__ void offsets_kernel() {
    if (threadIdx.x == 0) {
        int s = 0;
        for (int e = 0; e < NE; e++) { g_offset[e] = s; s += g_count[e]; }
    }
}

// ---------------------------------------------------------------- mma.sync GEMM
// A (gathered x or h) and B (weights) both K-major bf16 hi/lo.
// 128x128x32 tiles, 8 warps (2x4), 64x32 per warp, 3 split passes share accum.
template <int PHASE>
__global__ __launch_bounds__(256, 1) void gemm_mma_kernel(const float* __restrict__ bias) {
    constexpr int KD = (PHASE == 1) ? DIN : HID;
    constexpr int ND = (PHASE == 1) ? HID : DOUT;
    constexpr int NK = KD / BK;
    constexpr bool GATHER = (PHASE == 1);

    int e = blockIdx.x / MT_MAX, mt = blockIdx.x % MT_MAX;
    int cnt = g_count[e];
    int m0 = mt * BM;
    if (m0 >= cnt) return;
    int n0 = blockIdx.y * BN;
    int base = g_offset[e];
    size_t arow0 = (size_t)(base + m0);

    extern __shared__ char smem[];
    int* toks = (int*)smem;
    float* sbias = (float*)(smem + 512);
    uint32_t stgu = smem_to_u32(smem) + 1024;

    int tid = threadIdx.x, wid = tid >> 5, lane = tid & 31;
    int warp_m = wid >> 2, warp_n = wid & 3;

    if (GATHER && tid < BM) {
        int rr = m0 + tid;
        toks[tid] = (rr < cnt) ? g_tokens[e * T + rr] : -1;
    }
    if (tid < BN) sbias[tid] = bias[(size_t)e * ND + n0 + tid];
    __syncthreads();

    const __nv_bfloat16* Ahi = (PHASE == 1) ? g_xhi : g_hhi;
    const __nv_bfloat16* Alo = (PHASE == 1) ? g_xlo : g_hlo;
    const __nv_bfloat16* Bhi = (PHASE == 1) ? g_w1hi : g_w2hi;
    const __nv_bfloat16* Blo = (PHASE == 1) ? g_w1lo : g_w2lo;

    // per-thread load slots: 8 x 16B chunks per stage
    const __nv_bfloat16* gb[8];
    uint32_t so[8], sz[8];
#pragma unroll
    for (int i = 0; i < 8; i++) {
        int id = tid + i * 256;
        int mat = id >> 9;          // 0 Ahi, 1 Alo, 2 Bhi, 3 Blo
        int idx = id & 511;
        int row = idx >> 2, c = idx & 3;
        so[i] = (uint32_t)(mat * MAT_BYTES + row * ROWB + c * 16);
        if (mat < 2) {
            bool valid; size_t srow;
            if (GATHER) { int tk = toks[row]; valid = (tk >= 0); srow = (size_t)(valid ? tk : 0); }
            else        { valid = (m0 + row) < cnt; srow = arow0 + (valid ? row : 0); }
            gb[i] = ((mat == 0) ? Ahi : Alo) + srow * KD + c * 8;
            sz[i] = valid ? 16u : 0u;
        } else {
            gb[i] = ((mat == 2) ? Bhi : Blo) + ((size_t)e * ND + n0 + row) * KD + c * 8;
            sz[i] = 16u;
        }
    }

    auto issue = [&](int ck) {
        size_t koff = (size_t)ck * BK;
        uint32_t sdst = stgu + (uint32_t)((ck % NSTAGE) * STG_BYTES);
#pragma unroll
        for (int i = 0; i < 8; i++)
            cp_async16(sdst + so[i], gb[i] + koff, sz[i]);
    };

    float acc[4][4][4];
#pragma unroll
    for (int a = 0; a < 4; a++)
#pragma unroll
        for (int b = 0; b < 4; b++)
#pragma unroll
            for (int r = 0; r < 4; r++) acc[a][b][r] = 0.f;

    uint32_t a_off = (uint32_t)((warp_m * 64 + (lane & 15)) * ROWB + (lane >> 4) * 16);
    uint32_t b_off = (uint32_t)((warp_n * 32 + (lane & 15)) * ROWB + (lane >> 4) * 16);

#pragma unroll
    for (int s = 0; s < NSTAGE - 1; s++) { issue(s); CP_COMMIT(); }

    for (int ck = 0; ck < NK; ck++) {
        CP_WAIT(NSTAGE - 2);
        __syncthreads();
        int nk2 = ck + NSTAGE - 1;
        if (nk2 < NK) issue(nk2);
        CP_COMMIT();

        uint32_t sbase = stgu + (uint32_t)((ck % NSTAGE) * STG_BYTES);
        uint32_t sAh = sbase, sAl = sbase + MAT_BYTES;
        uint32_t sBh = sbase + 2 * MAT_BYTES, sBl = sbase + 3 * MAT_BYTES;
#pragma unroll
        for (int ks = 0; ks < 2; ks++) {
            uint32_t bh[8], bl[8];
#pragma unroll
            for (int p = 0; p < 2; p++) {
                ldmx4(&bh[p * 4], sBh + b_off + p * (16 * ROWB) + ks * 32);
                ldmx4(&bl[p * 4], sBl + b_off + p * (16 * ROWB) + ks * 32);
            }
#pragma unroll
            for (int fm = 0; fm < 4; fm++) {
                uint32_t ah[4], al[4];
                ldmx4(ah, sAh + a_off + fm * (16 * ROWB) + ks * 32);
                ldmx4(al, sAl + a_off + fm * (16 * ROWB) + ks * 32);
#pragma unroll
                for (int fn = 0; fn < 4; fn++) {
                    int p = fn >> 1, q = fn & 1;
                    uint32_t h0 = bh[p * 4 + q], h1 = bh[p * 4 + 2 + q];
                    mma_bf16(acc[fm][fn], ah, h0, h1);
                    mma_bf16(acc[fm][fn], ah, bl[p * 4 + q], bl[p * 4 + 2 + q]);
                    mma_bf16(acc[fm][fn], al, h0, h1);
                }
            }
        }
    }

    // ---------------- epilogue ----------------
#pragma unroll
    for (int fm = 0; fm < 4; fm++) {
#pragma unroll
        for (int fn = 0; fn < 4; fn++) {
            int col = warp_n * 32 + fn * 8 + (lane & 3) * 2;
            float bv0 = sbias[col], bv1 = sbias[col + 1];
#pragma unroll
            for (int h = 0; h < 2; h++) {
                int row = warp_m * 64 + fm * 16 + (lane >> 2) + h * 8;
                if (m0 + row >= cnt) continue;
                size_t crow = arow0 + row;
                float v0 = acc[fm][fn][h * 2 + 0] + bv0;
                float v1 = acc[fm][fn][h * 2 + 1] + bv1;
                if (PHASE == 1) {
                    v0 = fmaxf(v0, 0.f); v1 = fmaxf(v1, 0.f);
                    __nv_bfloat16 h0 = __float2bfloat16(v0);
                    __nv_bfloat16 h1 = __float2bfloat16(v1);
                    __nv_bfloat16 l0 = __float2bfloat16(v0 - __bfloat162float(h0));
                    __nv_bfloat16 l1 = __float2bfloat16(v1 - __bfloat162float(h1));
                    union { unsigned short u[2]; uint32_t w; } ph, pl;
                    ph.u[0] = *(unsigned short*)&h0; ph.u[1] = *(unsigned short*)&h1;
                    pl.u[0] = *(unsigned short*)&l0; pl.u[1] = *(unsigned short*)&l1;
                    size_t o = crow * (size_t)ND + n0 + col;
                    *(uint32_t*)(g_hhi + o) = ph.w;
                    *(uint32_t*)(g_hlo + o) = pl.w;
                } else {
                    float2 v; v.x = v0; v.y = v1;
                    *(float2*)(g_O + crow * (size_t)ND + n0 + col) = v;
                }
            }
        }
    }
}

// ---------------------------------------------------------------- combine
__global__ void combine_kernel(float* __restrict__ out) {
    int t = blockIdx.x;
    int e0 = g_tok_e[2 * t], e1 = g_tok_e[2 * t + 1];
    int r0 = g_offset[e0] + g_tok_pos[2 * t];
    int r1 = g_offset[e1] + g_tok_pos[2 * t + 1];
    float w0 = g_tok_w[2 * t], w1 = g_tok_w[2 * t + 1];
    const float4* a = (const float4*)(g_O + (size_t)r0 * DOUT);
    const float4* b = (const float4*)(g_O + (size_t)r1 * DOUT);
    float4* o = (float4*)(out + (size_t)t * DOUT);
    for (int i = threadIdx.x; i < DOUT / 4; i += blockDim.x) {
        float4 av = a[i], bv = b[i];
        float4 r;
        r.x = w0 * av.x + w1 * bv.x;
        r.y = w0 * av.y + w1 * bv.y;
        r.z = w0 * av.z + w1 * bv.z;
        r.w = w0 * av.w + w1 * bv.w;
        o[i] = r;
    }
}

// ---------------------------------------------------------------- launch
extern "C" void kernel_launch(void* const* d_in, const int* in_sizes, int n_in,
                              void* d_out, int out_size) {
    const float* x       = (const float*)d_in[0];
    const float* noise   = (const float*)d_in[1];
    const float* gate_w  = (const float*)d_in[2];
    const float* gate_b  = (const float*)d_in[3];
    const float* noise_w = (const float*)d_in[4];
    const float* noise_b = (const float*)d_in[5];
    const float* w1      = (const float*)d_in[6];
    const float* b1      = (const float*)d_in[7];
    const float* w2      = (const float*)d_in[8];
    const float* b2      = (const float*)d_in[9];
    float* out = (float*)d_out;

    float* w_out;
    if (out_size >= T * DOUT + T * NE) {
        w_out = out + (size_t)T * DOUT;
    } else {
        cudaGetSymbolAddress((void**)&w_out, g_wdummy);
    }

    cudaFuncSetAttribute(gemm_mma_kernel<1>, cudaFuncAttributeMaxDynamicSharedMemorySize, SMEM_TOT);
    cudaFuncSetAttribute(gemm_mma_kernel<2>, cudaFuncAttributeMaxDynamicSharedMemorySize, SMEM_TOT);

    zero_counts_kernel<<<1, 32>>>();
    split_x_kernel<<<(T * DIN / 4 + 255) / 256, 256>>>(x);
    tsplit_kernel<1><<<dim3(HID / 32, DIN / 32, NE), dim3(32, 8)>>>(w1);
    tsplit_kernel<2><<<dim3(DOUT / 32, HID / 32, NE), dim3(32, 8)>>>(w2);
    gating_kernel<<<T / 4, 128>>>(x, noise, gate_w, gate_b, noise_w, noise_b, w_out);
    offsets_kernel<<<1, 32>>>();
    gemm_mma_kernel<1><<<dim3(NE * MT_MAX, HID / BN), 256, SMEM_TOT>>>(b1);
    gemm_mma_kernel<2><<<dim3(NE * MT_MAX, DOUT / BN), 256, SMEM_TOT>>>(b2);
    combine_kernel<<<T, 256>>>(out);
}

// round 4
// speedup vs baseline: 2.5689x; 1.2571x over previous
#include <cuda_runtime.h>
#include <cuda_bf16.h>
#include <math.h>
#include <stdint.h>

#define T      4096
#define DIN    1024
#define DOUT   1024
#define NE     8
#define HID    4096
#define BM     256
#define BN     128
#define BK     64
#define MT     16          // max M tiles per expert (cnt can reach 4096)

// smem stage layout: 128B rows, SW128 swizzle
#define SM_AHI 0
#define SM_ALO 32768
#define SM_BHI 65536
#define SM_BLO 81920
#define STG_BYTES 98304
#define SMEM_TOT (2048 + 2 * STG_BYTES)   // 198656

// ---------------------------------------------------------------- helpers
__device__ __forceinline__ uint32_t smem_to_u32(const void* p) {
    uint32_t a;
    asm("{ .reg .u64 t; cvta.to.shared.u64 t, %1; cvt.u32.u64 %0, t; }" : "=r"(a) : "l"(p));
    return a;
}
__device__ __forceinline__ void ldmx4(uint32_t* r, uint32_t addr) {
    asm volatile("ldmatrix.sync.aligned.m8n8.x4.shared.b16 {%0,%1,%2,%3}, [%4];"
                 : "=r"(r[0]), "=r"(r[1]), "=r"(r[2]), "=r"(r[3]) : "r"(addr));
}
__device__ __forceinline__ void mma_bf16(float* c, const uint32_t* a, uint32_t b0, uint32_t b1) {
    asm volatile("mma.sync.aligned.m16n8k16.row.col.f32.bf16.bf16.f32 "
                 "{%0,%1,%2,%3}, {%4,%5,%6,%7}, {%8,%9}, {%0,%1,%2,%3};"
                 : "+f"(c[0]), "+f"(c[1]), "+f"(c[2]), "+f"(c[3])
                 : "r"(a[0]), "r"(a[1]), "r"(a[2]), "r"(a[3]), "r"(b0), "r"(b1));
}
__device__ __forceinline__ void cp_async16(uint32_t dst, const void* src, uint32_t sz) {
    asm volatile("cp.async.cg.shared.global [%0], [%1], 16, %2;"
                 :: "r"(dst), "l"(src), "r"(sz));
}
#define CP_COMMIT() asm volatile("cp.async.commit_group;")
#define CP_WAIT(n)  asm volatile("cp.async.wait_group %0;" :: "n"(n))
#define SMEM_SWZ(o) ((o) ^ (((o) >> 3) & 0x70))

// ---------------------------------------------------------------- device state
__device__ int   g_count[NE];
__device__ int   g_offset[NE];
__device__ int   g_tokens[NE * T];
__device__ int   g_tok_e[T * 2];
__device__ int   g_tok_pos[T * 2];
__device__ float g_tok_w[T * 2];
__device__ __align__(16) __nv_bfloat16 g_xhi[(size_t)T * DIN];
__device__ __align__(16) __nv_bfloat16 g_xlo[(size_t)T * DIN];
__device__ __align__(16) __nv_bfloat16 g_w1hi[(size_t)NE * HID * DIN];  // [e][n(H)][k(DIN)]
__device__ __align__(16) __nv_bfloat16 g_w1lo[(size_t)NE * HID * DIN];
__device__ __align__(16) __nv_bfloat16 g_w2hi[(size_t)NE * DOUT * HID]; // [e][n(O)][k(H)]
__device__ __align__(16) __nv_bfloat16 g_w2lo[(size_t)NE * DOUT * HID];
__device__ __align__(16) __nv_bfloat16 g_hhi[(size_t)T * 2 * HID];
__device__ __align__(16) __nv_bfloat16 g_hlo[(size_t)T * 2 * HID];
__device__ __align__(16) float g_O[(size_t)T * 2 * DOUT];
__device__ float g_wdummy[T * NE];

// ---------------------------------------------------------------- small kernels
__global__ void zero_counts_kernel() {
    if (threadIdx.x < NE) g_count[threadIdx.x] = 0;
}

__global__ void split_x_kernel(const float* __restrict__ x) {
    int i = blockIdx.x * blockDim.x + threadIdx.x;
    if (i >= T * DIN / 4) return;
    float4 v = ((const float4*)x)[i];
    union { unsigned short u[4]; uint2 p; } ph, pl;
    float vv[4] = {v.x, v.y, v.z, v.w};
#pragma unroll
    for (int j = 0; j < 4; j++) {
        __nv_bfloat16 h = __float2bfloat16(vv[j]);
        __nv_bfloat16 l = __float2bfloat16(vv[j] - __bfloat162float(h));
        ph.u[j] = *(unsigned short*)&h;
        pl.u[j] = *(unsigned short*)&l;
    }
    ((uint2*)g_xhi)[i] = ph.p;
    ((uint2*)g_xlo)[i] = pl.p;
}

// W [e][Kd][Nd] row-major -> hi/lo [e][Nd][Kd] (K-major, transposed)
template <int WHICH>
__global__ void tsplit_kernel(const float* __restrict__ W) {
    constexpr int Kd = (WHICH == 1) ? DIN : HID;
    constexpr int Nd = (WHICH == 1) ? HID : DOUT;
    __nv_bfloat16* hi = (WHICH == 1) ? g_w1hi : g_w2hi;
    __nv_bfloat16* lo = (WHICH == 1) ? g_w1lo : g_w2lo;
    int e = blockIdx.z;
    int n0 = blockIdx.x * 32, k0 = blockIdx.y * 32;
    __shared__ float tile[32][33];
    const float* We = W + (size_t)e * Kd * Nd;
    int tx = threadIdx.x, ty = threadIdx.y;
#pragma unroll
    for (int r = ty; r < 32; r += 8)
        tile[r][tx] = We[(size_t)(k0 + r) * Nd + n0 + tx];
    __syncthreads();
    size_t ob = (size_t)e * Nd * Kd;
#pragma unroll
    for (int r = ty; r < 32; r += 8) {
        int n = n0 + r, k = k0 + tx;
        float v = tile[tx][r];
        __nv_bfloat16 hv = __float2bfloat16(v);
        hi[ob + (size_t)n * Kd + k] = hv;
        lo[ob + (size_t)n * Kd + k] = __float2bfloat16(v - __bfloat162float(hv));
    }
}

__global__ void gating_kernel(const float* __restrict__ x,
                              const float* __restrict__ noise,
                              const float* __restrict__ gate_w,
                              const float* __restrict__ gate_b,
                              const float* __restrict__ noise_w,
                              const float* __restrict__ noise_b,
                              float* __restrict__ w_out) {
    int warp = blockIdx.x * (blockDim.x >> 5) + (threadIdx.x >> 5);
    int lane = threadIdx.x & 31;
    if (warp >= T) return;
    const float* xr = x + (size_t)warp * DIN;

    float ag[NE], an[NE];
#pragma unroll
    for (int e = 0; e < NE; e++) { ag[e] = 0.f; an[e] = 0.f; }
    for (int ii = 0; ii < DIN / 32; ii++) {
        int i = ii * 32 + lane;
        float xv = xr[i];
        float4 g0 = *(const float4*)(gate_w + (size_t)i * NE);
        float4 g1 = *(const float4*)(gate_w + (size_t)i * NE + 4);
        float4 n0 = *(const float4*)(noise_w + (size_t)i * NE);
        float4 n1 = *(const float4*)(noise_w + (size_t)i * NE + 4);
        ag[0] = fmaf(xv, g0.x, ag[0]); ag[1] = fmaf(xv, g0.y, ag[1]);
        ag[2] = fmaf(xv, g0.z, ag[2]); ag[3] = fmaf(xv, g0.w, ag[3]);
        ag[4] = fmaf(xv, g1.x, ag[4]); ag[5] = fmaf(xv, g1.y, ag[5]);
        ag[6] = fmaf(xv, g1.z, ag[6]); ag[7] = fmaf(xv, g1.w, ag[7]);
        an[0] = fmaf(xv, n0.x, an[0]); an[1] = fmaf(xv, n0.y, an[1]);
        an[2] = fmaf(xv, n0.z, an[2]); an[3] = fmaf(xv, n0.w, an[3]);
        an[4] = fmaf(xv, n1.x, an[4]); an[5] = fmaf(xv, n1.y, an[5]);
        an[6] = fmaf(xv, n1.z, an[6]); an[7] = fmaf(xv, n1.w, an[7]);
    }
#pragma unroll
    for (int e = 0; e < NE; e++) {
#pragma unroll
        for (int o = 16; o > 0; o >>= 1) {
            ag[e] += __shfl_xor_sync(0xffffffffu, ag[e], o);
            an[e] += __shfl_xor_sync(0xffffffffu, an[e], o);
        }
    }
    if (lane == 0) {
        float l[NE];
#pragma unroll
        for (int e = 0; e < NE; e++) {
            float z = an[e] + noise_b[e];
            float sp = (z > 20.f) ? z : log1pf(expf(z));
            l[e] = ag[e] + gate_b[e] + noise[(size_t)warp * NE + e] * sp;
        }
        int i0 = 0; float v0 = l[0];
#pragma unroll
        for (int e = 1; e < NE; e++) if (l[e] > v0) { v0 = l[e]; i0 = e; }
        int i1 = -1; float v1 = -INFINITY;
#pragma unroll
        for (int e = 0; e < NE; e++) if (e != i0 && l[e] > v1) { v1 = l[e]; i1 = e; }
        float eb = expf(v1 - v0);
        float w0 = 1.f / (1.f + eb);
        float w1 = eb / (1.f + eb);
        float wrow[NE];
#pragma unroll
        for (int e = 0; e < NE; e++) wrow[e] = 0.f;
        wrow[i0] = w0; wrow[i1] = w1;
#pragma unroll
        for (int e = 0; e < NE; e++) w_out[(size_t)warp * NE + e] = wrow[e];
        int p0 = atomicAdd(&g_count[i0], 1);
        int p1 = atomicAdd(&g_count[i1], 1);
        g_tokens[i0 * T + p0] = warp;
        g_tokens[i1 * T + p1] = warp;
        g_tok_e[2 * warp]     = i0; g_tok_pos[2 * warp]     = p0; g_tok_w[2 * warp]     = w0;
        g_tok_e[2 * warp + 1] = i1; g_tok_pos[2 * warp + 1] = p1; g_tok_w[2 * warp + 1] = w1;
    }
}

__global__ void offsets_kernel() {
    if (threadIdx.x == 0) {
        int s = 0;
        for (int e = 0; e < NE; e++) { g_offset[e] = s; s += g_count[e]; }
    }
}

// ---------------------------------------------------------------- mma.sync GEMM
// 256x128x64 tiles, 8 warps (2x4 grid, 128x32 per warp), 2-stage cp.async,
// SW128-swizzled 128B smem rows, 3 bf16-split passes (hh + hl + lh).
template <int PHASE>
__global__ __launch_bounds__(256, 1) void gemm_mma_kernel(const float* __restrict__ bias) {
    constexpr int KD = (PHASE == 1) ? DIN : HID;
    constexpr int ND = (PHASE == 1) ? HID : DOUT;
    constexpr int NT = ND / BN;
    constexpr int NK = KD / BK;
    constexpr bool GATHER = (PHASE == 1);

    int e = blockIdx.x / NT, nt = blockIdx.x % NT;
    int mt = blockIdx.y;
    int cnt = g_count[e];
    int m0 = mt * BM;
    if (m0 >= cnt) return;
    int n0 = nt * BN;
    int base = g_offset[e];
    size_t arow0 = (size_t)(base + m0);

    extern __shared__ char smem[];
    int* toks = (int*)smem;                    // 256 ints
    float* sbias = (float*)(smem + 1024);      // 128 floats
    uint32_t stgu = smem_to_u32(smem) + 2048;

    int tid = threadIdx.x, wid = tid >> 5, lane = tid & 31;
    int warp_m = wid >> 2, warp_n = wid & 3;

    if (GATHER) {
        int rr = m0 + tid;
        toks[tid] = (rr < cnt) ? g_tokens[e * T + rr] : -1;
    }
    if (tid < BN) sbias[tid] = bias[(size_t)e * ND + n0 + tid];
    __syncthreads();

    const __nv_bfloat16* Ahi = (PHASE == 1) ? g_xhi : g_hhi;
    const __nv_bfloat16* Alo = (PHASE == 1) ? g_xlo : g_hlo;
    const __nv_bfloat16* Bhi = (PHASE == 1) ? g_w1hi : g_w2hi;
    const __nv_bfloat16* Blo = (PHASE == 1) ? g_w1lo : g_w2lo;

    // per-thread load slots: row base rb (0..31), chunk col cc (0..7)
    int rb = tid >> 3, cc = tid & 7;
    uint32_t aoff[8], asz[8], sdA[8];
#pragma unroll
    for (int j = 0; j < 8; j++) {
        int row = rb + 32 * j;
        bool valid; size_t srow;
        if (GATHER) { int tk = toks[row]; valid = (tk >= 0); srow = (size_t)(valid ? tk : 0); }
        else        { valid = (m0 + row) < cnt; srow = arow0 + (valid ? row : 0); }
        aoff[j] = (uint32_t)(srow * KD + cc * 8);
        asz[j] = valid ? 16u : 0u;
        sdA[j] = SMEM_SWZ((uint32_t)(row * 128 + cc * 16));
    }
    uint32_t boff[4], sdB[4];
#pragma unroll
    for (int j = 0; j < 4; j++) {
        int row = rb + 32 * j;
        boff[j] = (uint32_t)(((size_t)e * ND + n0 + row) * KD + cc * 8);
        sdB[j] = SMEM_SWZ((uint32_t)(row * 128 + cc * 16));
    }

    auto issue = [&](int ck) {
        uint32_t st = stgu + (uint32_t)((ck & 1) * STG_BYTES);
        uint32_t ko = (uint32_t)(ck * BK);
#pragma unroll
        for (int j = 0; j < 8; j++) cp_async16(st + SM_AHI + sdA[j], Ahi + aoff[j] + ko, asz[j]);
#pragma unroll
        for (int j = 0; j < 8; j++) cp_async16(st + SM_ALO + sdA[j], Alo + aoff[j] + ko, asz[j]);
#pragma unroll
        for (int j = 0; j < 4; j++) cp_async16(st + SM_BHI + sdB[j], Bhi + boff[j] + ko, 16u);
#pragma unroll
        for (int j = 0; j < 4; j++) cp_async16(st + SM_BLO + sdB[j], Blo + boff[j] + ko, 16u);
    };

    float acc[8][4][4];
#pragma unroll
    for (int a = 0; a < 8; a++)
#pragma unroll
        for (int b = 0; b < 4; b++)
#pragma unroll
            for (int r = 0; r < 4; r++) acc[a][b][r] = 0.f;

    issue(0); CP_COMMIT();

    for (int ck = 0; ck < NK; ck++) {
        CP_WAIT(0);
        __syncthreads();
        if (ck + 1 < NK) issue(ck + 1);
        CP_COMMIT();

        uint32_t sbase = stgu + (uint32_t)((ck & 1) * STG_BYTES);
#pragma unroll
        for (int ks = 0; ks < 4; ks++) {
            uint32_t bh[8], bl[8];
#pragma unroll
            for (int p = 0; p < 2; p++) {
                uint32_t bo = SMEM_SWZ((uint32_t)((warp_n * 32 + p * 16 + (lane & 15)) * 128 +
                                                  ks * 32 + (lane >> 4) * 16));
                ldmx4(&bh[p * 4], sbase + SM_BHI + bo);
                ldmx4(&bl[p * 4], sbase + SM_BLO + bo);
            }
#pragma unroll
            for (int fm = 0; fm < 8; fm++) {
                uint32_t ao = SMEM_SWZ((uint32_t)((warp_m * 128 + fm * 16 + (lane & 15)) * 128 +
                                                  ks * 32 + (lane >> 4) * 16));
                uint32_t ah[4], al[4];
                ldmx4(ah, sbase + SM_AHI + ao);
                ldmx4(al, sbase + SM_ALO + ao);
#pragma unroll
                for (int fn = 0; fn < 4; fn++) {
                    int p = fn >> 1, q = fn & 1;
                    uint32_t h0 = bh[p * 4 + q], h1 = bh[p * 4 + 2 + q];
                    mma_bf16(acc[fm][fn], ah, h0, h1);
                    mma_bf16(acc[fm][fn], ah, bl[p * 4 + q], bl[p * 4 + 2 + q]);
                    mma_bf16(acc[fm][fn], al, h0, h1);
                }
            }
        }
    }

    // ---------------- epilogue ----------------
#pragma unroll
    for (int fm = 0; fm < 8; fm++) {
#pragma unroll
        for (int fn = 0; fn < 4; fn++) {
            int col = warp_n * 32 + fn * 8 + (lane & 3) * 2;
            float bv0 = sbias[col], bv1 = sbias[col + 1];
#pragma unroll
            for (int h = 0; h < 2; h++) {
                int row = warp_m * 128 + fm * 16 + (lane >> 2) + h * 8;
                if (m0 + row >= cnt) continue;
                size_t crow = arow0 + row;
                float v0 = acc[fm][fn][h * 2 + 0] + bv0;
                float v1 = acc[fm][fn][h * 2 + 1] + bv1;
                if (PHASE == 1) {
                    v0 = fmaxf(v0, 0.f); v1 = fmaxf(v1, 0.f);
                    __nv_bfloat16 h0 = __float2bfloat16(v0);
                    __nv_bfloat16 h1 = __float2bfloat16(v1);
                    __nv_bfloat16 l0 = __float2bfloat16(v0 - __bfloat162float(h0));
                    __nv_bfloat16 l1 = __float2bfloat16(v1 - __bfloat162float(h1));
                    union { unsigned short u[2]; uint32_t w; } ph, pl;
                    ph.u[0] = *(unsigned short*)&h0; ph.u[1] = *(unsigned short*)&h1;
                    pl.u[0] = *(unsigned short*)&l0; pl.u[1] = *(unsigned short*)&l1;
                    size_t o = crow * (size_t)ND + n0 + col;
                    *(uint32_t*)(g_hhi + o) = ph.w;
                    *(uint32_t*)(g_hlo + o) = pl.w;
                } else {
                    float2 v; v.x = v0; v.y = v1;
                    *(float2*)(g_O + crow * (size_t)ND + n0 + col) = v;
                }
            }
        }
    }
}

// ---------------------------------------------------------------- combine
__global__ void combine_kernel(float* __restrict__ out) {
    int t = blockIdx.x;
    int e0 = g_tok_e[2 * t], e1 = g_tok_e[2 * t + 1];
    int r0 = g_offset[e0] + g_tok_pos[2 * t];
    int r1 = g_offset[e1] + g_tok_pos[2 * t + 1];
    float w0 = g_tok_w[2 * t], w1 = g_tok_w[2 * t + 1];
    const float4* a = (const float4*)(g_O + (size_t)r0 * DOUT);
    const float4* b = (const float4*)(g_O + (size_t)r1 * DOUT);
    float4* o = (float4*)(out + (size_t)t * DOUT);
    for (int i = threadIdx.x; i < DOUT / 4; i += blockDim.x) {
        float4 av = a[i], bv = b[i];
        float4 r;
        r.x = w0 * av.x + w1 * bv.x;
        r.y = w0 * av.y + w1 * bv.y;
        r.z = w0 * av.z + w1 * bv.z;
        r.w = w0 * av.w + w1 * bv.w;
        o[i] = r;
    }
}

// ---------------------------------------------------------------- launch
extern "C" void kernel_launch(void* const* d_in, const int* in_sizes, int n_in,
                              void* d_out, int out_size) {
    const float* x       = (const float*)d_in[0];
    const float* noise   = (const float*)d_in[1];
    const float* gate_w  = (const float*)d_in[2];
    const float* gate_b  = (const float*)d_in[3];
    const float* noise_w = (const float*)d_in[4];
    const float* noise_b = (const float*)d_in[5];
    const float* w1      = (const float*)d_in[6];
    const float* b1      = (const float*)d_in[7];
    const float* w2      = (const float*)d_in[8];
    const float* b2      = (const float*)d_in[9];
    float* out = (float*)d_out;

    float* w_out;
    if (out_size >= T * DOUT + T * NE) {
        w_out = out + (size_t)T * DOUT;
    } else {
        cudaGetSymbolAddress((void**)&w_out, g_wdummy);
    }

    cudaFuncSetAttribute(gemm_mma_kernel<1>, cudaFuncAttributeMaxDynamicSharedMemorySize, SMEM_TOT);
    cudaFuncSetAttribute(gemm_mma_kernel<2>, cudaFuncAttributeMaxDynamicSharedMemorySize, SMEM_TOT);

    zero_counts_kernel<<<1, 32>>>();
    split_x_kernel<<<(T * DIN / 4 + 255) / 256, 256>>>(x);
    tsplit_kernel<1><<<dim3(HID / 32, DIN / 32, NE), dim3(32, 8)>>>(w1);
    tsplit_kernel<2><<<dim3(DOUT / 32, HID / 32, NE), dim3(32, 8)>>>(w2);
    gating_kernel<<<T / 4, 128>>>(x, noise, gate_w, gate_b, noise_w, noise_b, w_out);
    offsets_kernel<<<1, 32>>>();
    gemm_mma_kernel<1><<<dim3(NE * (HID / BN), MT), 256, SMEM_TOT>>>(b1);
    gemm_mma_kernel<2><<<dim3(NE * (DOUT / BN), MT), 256, SMEM_TOT>>>(b2);
    combine_kernel<<<T, 256>>>(out);
}

// round 5
// speedup vs baseline: 2.9344x; 1.1423x over previous
#include <cuda_runtime.h>
#include <cuda_bf16.h>
#include <math.h>
#include <stdint.h>

#define T      4096
#define DIN    1024
#define DOUT   1024
#define NE     8
#define HID    4096
#define BM     128
#define BN     256
#define BK     64
#define MT     32

// smem stage: A hi/lo 128x128B each, B hi/lo 64x512B each
#define SM_AHI 0
#define SM_ALO 16384
#define SM_BHI 32768
#define SM_BLO 65536
#define STG_BYTES 98304
#define SMEM_TOT (2048 + 2 * STG_BYTES)   // 198656

// ---------------------------------------------------------------- helpers
__device__ __forceinline__ uint32_t smem_to_u32(const void* p) {
    uint32_t a;
    asm("{ .reg .u64 t; cvta.to.shared.u64 t, %1; cvt.u32.u64 %0, t; }" : "=r"(a) : "l"(p));
    return a;
}
__device__ __forceinline__ void ldmx4(uint32_t* r, uint32_t addr) {
    asm volatile("ldmatrix.sync.aligned.m8n8.x4.shared.b16 {%0,%1,%2,%3}, [%4];"
                 : "=r"(r[0]), "=r"(r[1]), "=r"(r[2]), "=r"(r[3]) : "r"(addr));
}
__device__ __forceinline__ void ldmx4t(uint32_t* r, uint32_t addr) {
    asm volatile("ldmatrix.sync.aligned.m8n8.x4.trans.shared.b16 {%0,%1,%2,%3}, [%4];"
                 : "=r"(r[0]), "=r"(r[1]), "=r"(r[2]), "=r"(r[3]) : "r"(addr));
}
__device__ __forceinline__ void mma_bf16(float* c, const uint32_t* a, uint32_t b0, uint32_t b1) {
    asm volatile("mma.sync.aligned.m16n8k16.row.col.f32.bf16.bf16.f32 "
                 "{%0,%1,%2,%3}, {%4,%5,%6,%7}, {%8,%9}, {%0,%1,%2,%3};"
                 : "+f"(c[0]), "+f"(c[1]), "+f"(c[2]), "+f"(c[3])
                 : "r"(a[0]), "r"(a[1]), "r"(a[2]), "r"(a[3]), "r"(b0), "r"(b1));
}
__device__ __forceinline__ void cp_async16(uint32_t dst, const void* src, uint32_t sz) {
    asm volatile("cp.async.cg.shared.global [%0], [%1], 16, %2;"
                 :: "r"(dst), "l"(src), "r"(sz));
}
#define CP_COMMIT() asm volatile("cp.async.commit_group;")
#define CP_WAIT(n)  asm volatile("cp.async.wait_group %0;" :: "n"(n))
#define SWZ_A(o) ((o) ^ (((o) >> 3) & 0x70))   // 128B rows
#define SWZ_B(o) ((o) ^ (((o) >> 5) & 0x70))   // 512B rows

// ---------------------------------------------------------------- device state
__device__ int   g_count[NE];
__device__ int   g_offset[NE];
__device__ int   g_tokens[NE * T];
__device__ int   g_tok_e[T * 2];
__device__ int   g_tok_pos[T * 2];
__device__ float g_tok_w[T * 2];
__device__ __align__(16) __nv_bfloat16 g_xhi[(size_t)T * DIN];
__device__ __align__(16) __nv_bfloat16 g_xlo[(size_t)T * DIN];
__device__ __align__(16) __nv_bfloat16 g_w1hi[(size_t)NE * DIN * HID];   // native [e][k][n]
__device__ __align__(16) __nv_bfloat16 g_w1lo[(size_t)NE * DIN * HID];
__device__ __align__(16) __nv_bfloat16 g_w2hi[(size_t)NE * HID * DOUT];  // native [e][k][n]
__device__ __align__(16) __nv_bfloat16 g_w2lo[(size_t)NE * HID * DOUT];
__device__ __align__(16) __nv_bfloat16 g_hhi[(size_t)T * 2 * HID];
__device__ __align__(16) __nv_bfloat16 g_hlo[(size_t)T * 2 * HID];
__device__ __align__(16) float g_O[(size_t)T * 2 * DOUT];
__device__ float g_wdummy[T * NE];

// ---------------------------------------------------------------- small kernels
__global__ void zero_counts_kernel() {
    if (threadIdx.x < NE) g_count[threadIdx.x] = 0;
}

// streaming fp32 -> bf16 hi/lo split (no transpose; layout preserved)
__global__ void split_kernel(const float* __restrict__ src,
                             __nv_bfloat16* __restrict__ hi,
                             __nv_bfloat16* __restrict__ lo, int n4) {
    int i = blockIdx.x * blockDim.x + threadIdx.x;
    if (i >= n4) return;
    float4 v = ((const float4*)src)[i];
    union { unsigned short u[4]; uint2 p; } ph, pl;
    float vv[4] = {v.x, v.y, v.z, v.w};
#pragma unroll
    for (int j = 0; j < 4; j++) {
        __nv_bfloat16 h = __float2bfloat16(vv[j]);
        __nv_bfloat16 l = __float2bfloat16(vv[j] - __bfloat162float(h));
        ph.u[j] = *(unsigned short*)&h;
        pl.u[j] = *(unsigned short*)&l;
    }
    ((uint2*)hi)[i] = ph.p;
    ((uint2*)lo)[i] = pl.p;
}

__global__ void gating_kernel(const float* __restrict__ x,
                              const float* __restrict__ noise,
                              const float* __restrict__ gate_w,
                              const float* __restrict__ gate_b,
                              const float* __restrict__ noise_w,
                              const float* __restrict__ noise_b,
                              float* __restrict__ w_out) {
    int warp = blockIdx.x * (blockDim.x >> 5) + (threadIdx.x >> 5);
    int lane = threadIdx.x & 31;
    if (warp >= T) return;
    const float* xr = x + (size_t)warp * DIN;

    float ag[NE], an[NE];
#pragma unroll
    for (int e = 0; e < NE; e++) { ag[e] = 0.f; an[e] = 0.f; }
    for (int ii = 0; ii < DIN / 32; ii++) {
        int i = ii * 32 + lane;
        float xv = xr[i];
        float4 g0 = *(const float4*)(gate_w + (size_t)i * NE);
        float4 g1 = *(const float4*)(gate_w + (size_t)i * NE + 4);
        float4 n0 = *(const float4*)(noise_w + (size_t)i * NE);
        float4 n1 = *(const float4*)(noise_w + (size_t)i * NE + 4);
        ag[0] = fmaf(xv, g0.x, ag[0]); ag[1] = fmaf(xv, g0.y, ag[1]);
        ag[2] = fmaf(xv, g0.z, ag[2]); ag[3] = fmaf(xv, g0.w, ag[3]);
        ag[4] = fmaf(xv, g1.x, ag[4]); ag[5] = fmaf(xv, g1.y, ag[5]);
        ag[6] = fmaf(xv, g1.z, ag[6]); ag[7] = fmaf(xv, g1.w, ag[7]);
        an[0] = fmaf(xv, n0.x, an[0]); an[1] = fmaf(xv, n0.y, an[1]);
        an[2] = fmaf(xv, n0.z, an[2]); an[3] = fmaf(xv, n0.w, an[3]);
        an[4] = fmaf(xv, n1.x, an[4]); an[5] = fmaf(xv, n1.y, an[5]);
        an[6] = fmaf(xv, n1.z, an[6]); an[7] = fmaf(xv, n1.w, an[7]);
    }
#pragma unroll
    for (int e = 0; e < NE; e++) {
#pragma unroll
        for (int o = 16; o > 0; o >>= 1) {
            ag[e] += __shfl_xor_sync(0xffffffffu, ag[e], o);
            an[e] += __shfl_xor_sync(0xffffffffu, an[e], o);
        }
    }
    if (lane == 0) {
        float l[NE];
#pragma unroll
        for (int e = 0; e < NE; e++) {
            float z = an[e] + noise_b[e];
            float sp = (z > 20.f) ? z : log1pf(expf(z));
            l[e] = ag[e] + gate_b[e] + noise[(size_t)warp * NE + e] * sp;
        }
        int i0 = 0; float v0 = l[0];
#pragma unroll
        for (int e = 1; e < NE; e++) if (l[e] > v0) { v0 = l[e]; i0 = e; }
        int i1 = -1; float v1 = -INFINITY;
#pragma unroll
        for (int e = 0; e < NE; e++) if (e != i0 && l[e] > v1) { v1 = l[e]; i1 = e; }
        float eb = expf(v1 - v0);
        float w0 = 1.f / (1.f + eb);
        float w1 = eb / (1.f + eb);
        float wrow[NE];
#pragma unroll
        for (int e = 0; e < NE; e++) wrow[e] = 0.f;
        wrow[i0] = w0; wrow[i1] = w1;
#pragma unroll
        for (int e = 0; e < NE; e++) w_out[(size_t)warp * NE + e] = wrow[e];
        int p0 = atomicAdd(&g_count[i0], 1);
        int p1 = atomicAdd(&g_count[i1], 1);
        g_tokens[i0 * T + p0] = warp;
        g_tokens[i1 * T + p1] = warp;
        g_tok_e[2 * warp]     = i0; g_tok_pos[2 * warp]     = p0; g_tok_w[2 * warp]     = w0;
        g_tok_e[2 * warp + 1] = i1; g_tok_pos[2 * warp + 1] = p1; g_tok_w[2 * warp + 1] = w1;
    }
}

__global__ void offsets_kernel() {
    if (threadIdx.x == 0) {
        int s = 0;
        for (int e = 0; e < NE; e++) { g_offset[e] = s; s += g_count[e]; }
    }
}

// ---------------------------------------------------------------- mma.sync GEMM
// 128x256x64 tiles, 8 warps (2x4, 64x64 each). A [m][k] K-major hi/lo; B kept in
// NATIVE [k][n] layout, consumed via ldmatrix.x4.trans. 3 bf16-split passes.
template <int PHASE>
__global__ __launch_bounds__(256, 1) void gemm_mma_kernel(const float* __restrict__ bias) {
    constexpr int KD = (PHASE == 1) ? DIN : HID;
    constexpr int ND = (PHASE == 1) ? HID : DOUT;
    constexpr int NT = ND / BN;
    constexpr int NK = KD / BK;
    constexpr bool GATHER = (PHASE == 1);

    int e = blockIdx.x / NT, nt = blockIdx.x % NT;
    int mt = blockIdx.y;
    int cnt = g_count[e];
    int m0 = mt * BM;
    if (m0 >= cnt) return;
    int n0 = nt * BN;
    int base = g_offset[e];
    size_t arow0 = (size_t)(base + m0);

    extern __shared__ char smem[];
    int* toks = (int*)smem;                    // 128 ints
    float* sbias = (float*)(smem + 1024);      // 256 floats
    uint32_t stgu = smem_to_u32(smem) + 2048;

    int tid = threadIdx.x, wid = tid >> 5, lane = tid & 31;
    int warp_m = wid >> 2, warp_n = wid & 3;

    if (GATHER && tid < BM) {
        int rr = m0 + tid;
        toks[tid] = (rr < cnt) ? g_tokens[e * T + rr] : -1;
    }
    sbias[tid] = bias[(size_t)e * ND + n0 + tid];
    __syncthreads();

    const __nv_bfloat16* Ahi = (PHASE == 1) ? g_xhi : g_hhi;
    const __nv_bfloat16* Alo = (PHASE == 1) ? g_xlo : g_hlo;
    const __nv_bfloat16* Bhi = (PHASE == 1) ? g_w1hi : g_w2hi;
    const __nv_bfloat16* Blo = (PHASE == 1) ? g_w1lo : g_w2lo;

    // A side: thread -> row r = tid>>1, chunks (tid&1)*4 + j (j<4)
    int ar = tid >> 1, asub = tid & 1;
    uint32_t aszA;
    const __nv_bfloat16 *aPhi, *aPlo;
    {
        bool valid; size_t srow;
        if (GATHER) { int tk = toks[ar]; valid = (tk >= 0); srow = (size_t)(valid ? tk : 0); }
        else        { valid = (m0 + ar) < cnt; srow = arow0 + (valid ? ar : 0); }
        aszA = valid ? 16u : 0u;
        aPhi = Ahi + srow * KD + asub * 32;
        aPlo = Alo + srow * KD + asub * 32;
    }
    uint32_t sdA[4];
#pragma unroll
    for (int j = 0; j < 4; j++)
        sdA[j] = SWZ_A((uint32_t)(ar * 128 + (asub * 4 + j) * 16));

    // B side: thread -> k-row kb = tid>>5 (+8j), chunk c = tid&31
    int kb = tid >> 5, bc = tid & 31;
    const __nv_bfloat16* bPhi = Bhi + ((size_t)e * KD + kb) * ND + n0 + bc * 8;
    const __nv_bfloat16* bPlo = Blo + ((size_t)e * KD + kb) * ND + n0 + bc * 8;
    uint32_t sdB[8];
#pragma unroll
    for (int j = 0; j < 8; j++)
        sdB[j] = SWZ_B((uint32_t)((kb + 8 * j) * 512 + bc * 16));

    auto issue = [&](int ck) {
        uint32_t st = stgu + (uint32_t)((ck & 1) * STG_BYTES);
        size_t koA = (size_t)ck * BK;
        size_t koB = (size_t)ck * BK * ND;
#pragma unroll
        for (int j = 0; j < 4; j++) {
            cp_async16(st + SM_AHI + sdA[j], aPhi + koA + j * 8, aszA);
            cp_async16(st + SM_ALO + sdA[j], aPlo + koA + j * 8, aszA);
        }
#pragma unroll
        for (int j = 0; j < 8; j++) {
            cp_async16(st + SM_BHI + sdB[j], bPhi + koB + (size_t)(8 * j) * ND, 16u);
            cp_async16(st + SM_BLO + sdB[j], bPlo + koB + (size_t)(8 * j) * ND, 16u);
        }
    };

    float acc[4][8][4];
#pragma unroll
    for (int a = 0; a < 4; a++)
#pragma unroll
        for (int b = 0; b < 8; b++)
#pragma unroll
            for (int r = 0; r < 4; r++) acc[a][b][r] = 0.f;

    issue(0); CP_COMMIT();

    for (int ck = 0; ck < NK; ck++) {
        CP_WAIT(0);
        __syncthreads();
        if (ck + 1 < NK) issue(ck + 1);
        CP_COMMIT();

        uint32_t sbase = stgu + (uint32_t)((ck & 1) * STG_BYTES);
#pragma unroll
        for (int ks = 0; ks < 4; ks++) {
            // B frags: 4 x4.trans hi + 4 lo -> 8 n8 frags each
            uint32_t bh[16], bl[16];
#pragma unroll
            for (int p = 0; p < 4; p++) {
                uint32_t bo = SWZ_B((uint32_t)((ks * 16 + (lane & 15)) * 512 +
                                               warp_n * 128 + p * 32 + (lane >> 4) * 16));
                ldmx4t(&bh[p * 4], sbase + SM_BHI + bo);
                ldmx4t(&bl[p * 4], sbase + SM_BLO + bo);
            }
#pragma unroll
            for (int fm = 0; fm < 4; fm++) {
                uint32_t ao = SWZ_A((uint32_t)((warp_m * 64 + fm * 16 + (lane & 15)) * 128 +
                                               ks * 32 + (lane >> 4) * 16));
                uint32_t ah[4], al[4];
                ldmx4(ah, sbase + SM_AHI + ao);
                ldmx4(al, sbase + SM_ALO + ao);
#pragma unroll
                for (int fn = 0; fn < 8; fn++) {
                    uint32_t h0 = bh[fn * 2], h1 = bh[fn * 2 + 1];
                    mma_bf16(acc[fm][fn], ah, h0, h1);
                    mma_bf16(acc[fm][fn], ah, bl[fn * 2], bl[fn * 2 + 1]);
                    mma_bf16(acc[fm][fn], al, h0, h1);
                }
            }
        }
    }

    // ---------------- epilogue ----------------
#pragma unroll
    for (int fm = 0; fm < 4; fm++) {
#pragma unroll
        for (int fn = 0; fn < 8; fn++) {
            int col = warp_n * 64 + fn * 8 + (lane & 3) * 2;
            float bv0 = sbias[col], bv1 = sbias[col + 1];
#pragma unroll
            for (int h = 0; h < 2; h++) {
                int row = warp_m * 64 + fm * 16 + (lane >> 2) + h * 8;
                if (m0 + row >= cnt) continue;
                size_t crow = arow0 + row;
                float v0 = acc[fm][fn][h * 2 + 0] + bv0;
                float v1 = acc[fm][fn][h * 2 + 1] + bv1;
                if (PHASE == 1) {
                    v0 = fmaxf(v0, 0.f); v1 = fmaxf(v1, 0.f);
                    __nv_bfloat16 h0 = __float2bfloat16(v0);
                    __nv_bfloat16 h1 = __float2bfloat16(v1);
                    __nv_bfloat16 l0 = __float2bfloat16(v0 - __bfloat162float(h0));
                    __nv_bfloat16 l1 = __float2bfloat16(v1 - __bfloat162float(h1));
                    union { unsigned short u[2]; uint32_t w; } ph, pl;
                    ph.u[0] = *(unsigned short*)&h0; ph.u[1] = *(unsigned short*)&h1;
                    pl.u[0] = *(unsigned short*)&l0; pl.u[1] = *(unsigned short*)&l1;
                    size_t o = crow * (size_t)ND + n0 + col;
                    *(uint32_t*)(g_hhi + o) = ph.w;
                    *(uint32_t*)(g_hlo + o) = pl.w;
                } else {
                    float2 v; v.x = v0; v.y = v1;
                    *(float2*)(g_O + crow * (size_t)ND + n0 + col) = v;
                }
            }
        }
    }
}

// ---------------------------------------------------------------- combine
__global__ void combine_kernel(float* __restrict__ out) {
    int t = blockIdx.x;
    int e0 = g_tok_e[2 * t], e1 = g_tok_e[2 * t + 1];
    int r0 = g_offset[e0] + g_tok_pos[2 * t];
    int r1 = g_offset[e1] + g_tok_pos[2 * t + 1];
    float w0 = g_tok_w[2 * t], w1 = g_tok_w[2 * t + 1];
    const float4* a = (const float4*)(g_O + (size_t)r0 * DOUT);
    const float4* b = (const float4*)(g_O + (size_t)r1 * DOUT);
    float4* o = (float4*)(out + (size_t)t * DOUT);
    for (int i = threadIdx.x; i < DOUT / 4; i += blockDim.x) {
        float4 av = a[i], bv = b[i];
        float4 r;
        r.x = w0 * av.x + w1 * bv.x;
        r.y = w0 * av.y + w1 * bv.y;
        r.z = w0 * av.z + w1 * bv.z;
        r.w = w0 * av.w + w1 * bv.w;
        o[i] = r;
    }
}

// ---------------------------------------------------------------- launch
extern "C" void kernel_launch(void* const* d_in, const int* in_sizes, int n_in,
                              void* d_out, int out_size) {
    const float* x       = (const float*)d_in[0];
    const float* noise   = (const float*)d_in[1];
    const float* gate_w  = (const float*)d_in[2];
    const float* gate_b  = (const float*)d_in[3];
    const float* noise_w = (const float*)d_in[4];
    const float* noise_b = (const float*)d_in[5];
    const float* w1      = (const float*)d_in[6];
    const float* b1      = (const float*)d_in[7];
    const float* w2      = (const float*)d_in[8];
    const float* b2      = (const float*)d_in[9];
    float* out = (float*)d_out;

    float* w_out;
    if (out_size >= T * DOUT + T * NE) {
        w_out = out + (size_t)T * DOUT;
    } else {
        cudaGetSymbolAddress((void**)&w_out, g_wdummy);
    }

    cudaFuncSetAttribute(gemm_mma_kernel<1>, cudaFuncAttributeMaxDynamicSharedMemorySize, SMEM_TOT);
    cudaFuncSetAttribute(gemm_mma_kernel<2>, cudaFuncAttributeMaxDynamicSharedMemorySize, SMEM_TOT);

    __nv_bfloat16 *xhi, *xlo, *w1hi, *w1lo, *w2hi, *w2lo;
    cudaGetSymbolAddress((void**)&xhi, g_xhi);
    cudaGetSymbolAddress((void**)&xlo, g_xlo);
    cudaGetSymbolAddress((void**)&w1hi, g_w1hi);
    cudaGetSymbolAddress((void**)&w1lo, g_w1lo);
    cudaGetSymbolAddress((void**)&w2hi, g_w2hi);
    cudaGetSymbolAddress((void**)&w2lo, g_w2lo);

    zero_counts_kernel<<<1, 32>>>();
    split_kernel<<<(T * DIN / 4 + 255) / 256, 256>>>(x, xhi, xlo, T * DIN / 4);
    split_kernel<<<(NE * DIN * HID / 4 + 255) / 256, 256>>>(w1, w1hi, w1lo, NE * DIN * HID / 4);
    split_kernel<<<(NE * HID * DOUT / 4 + 255) / 256, 256>>>(w2, w2hi, w2lo, NE * HID * DOUT / 4);
    gating_kernel<<<T / 4, 128>>>(x, noise, gate_w, gate_b, noise_w, noise_b, w_out);
    offsets_kernel<<<1, 32>>>();
    gemm_mma_kernel<1><<<dim3(NE * (HID / BN), MT), 256, SMEM_TOT>>>(b1);
    gemm_mma_kernel<2><<<dim3(NE * (DOUT / BN), MT), 256, SMEM_TOT>>>(b2);
    combine_kernel<<<T, 256>>>(out);
}

// round 6
// speedup vs baseline: 3.9620x; 1.3502x over previous
#include <cuda_runtime.h>
#include <cuda_fp16.h>
#include <math.h>
#include <stdint.h>

#define T      4096
#define DIN    1024
#define DOUT   1024
#define NE     8
#define HID    4096
#define BM     128
#define BN     256
#define BK     64
#define MT     32

// smem stage: A hi/lo 128x128B each (16KB ea), B single 64x512B (32KB)
#define SM_AHI 0
#define SM_ALO 16384
#define SM_B   32768
#define STG_BYTES 65536
#define NSTAGE 3
#define SMEM_TOT (2048 + NSTAGE * STG_BYTES)   // 198656

// ---------------------------------------------------------------- helpers
__device__ __forceinline__ uint32_t smem_to_u32(const void* p) {
    uint32_t a;
    asm("{ .reg .u64 t; cvta.to.shared.u64 t, %1; cvt.u32.u64 %0, t; }" : "=r"(a) : "l"(p));
    return a;
}
__device__ __forceinline__ void ldmx4(uint32_t* r, uint32_t addr) {
    asm volatile("ldmatrix.sync.aligned.m8n8.x4.shared.b16 {%0,%1,%2,%3}, [%4];"
                 : "=r"(r[0]), "=r"(r[1]), "=r"(r[2]), "=r"(r[3]) : "r"(addr));
}
__device__ __forceinline__ void ldmx4t(uint32_t* r, uint32_t addr) {
    asm volatile("ldmatrix.sync.aligned.m8n8.x4.trans.shared.b16 {%0,%1,%2,%3}, [%4];"
                 : "=r"(r[0]), "=r"(r[1]), "=r"(r[2]), "=r"(r[3]) : "r"(addr));
}
__device__ __forceinline__ void mma_f16(float* c, const uint32_t* a, uint32_t b0, uint32_t b1) {
    asm volatile("mma.sync.aligned.m16n8k16.row.col.f32.f16.f16.f32 "
                 "{%0,%1,%2,%3}, {%4,%5,%6,%7}, {%8,%9}, {%0,%1,%2,%3};"
                 : "+f"(c[0]), "+f"(c[1]), "+f"(c[2]), "+f"(c[3])
                 : "r"(a[0]), "r"(a[1]), "r"(a[2]), "r"(a[3]), "r"(b0), "r"(b1));
}
__device__ __forceinline__ void cp_async16(uint32_t dst, const void* src, uint32_t sz) {
    asm volatile("cp.async.cg.shared.global [%0], [%1], 16, %2;"
                 :: "r"(dst), "l"(src), "r"(sz));
}
#define CP_COMMIT() asm volatile("cp.async.commit_group;")
#define CP_WAIT(n)  asm volatile("cp.async.wait_group %0;" :: "n"(n))
#define SWZ_A(o) ((o) ^ (((o) >> 3) & 0x70))   // 128B rows
#define SWZ_B(o) ((o) ^ (((o) >> 5) & 0x70))   // 512B rows

// ---------------------------------------------------------------- device state
__device__ int   g_count[NE];
__device__ int   g_offset[NE];
__device__ int   g_tokens[NE * T];
__device__ int   g_tok_e[T * 2];
__device__ int   g_tok_pos[T * 2];
__device__ float g_tok_w[T * 2];
__device__ __align__(16) __half g_xhi[(size_t)T * DIN];
__device__ __align__(16) __half g_xlo[(size_t)T * DIN];
__device__ __align__(16) __half g_w1[(size_t)NE * DIN * HID];   // native [e][k][n]
__device__ __align__(16) __half g_w2[(size_t)NE * HID * DOUT];  // native [e][k][n]
__device__ __align__(16) __half g_hhi[(size_t)T * 2 * HID];
__device__ __align__(16) __half g_hlo[(size_t)T * 2 * HID];
__device__ __align__(16) float g_O[(size_t)T * 2 * DOUT];
__device__ float g_wdummy[T * NE];

// ---------------------------------------------------------------- small kernels
__global__ void zero_counts_kernel() {
    if (threadIdx.x < NE) g_count[threadIdx.x] = 0;
}

// fp32 -> fp16 plain convert (weights)
__global__ void conv_kernel(const float* __restrict__ src, __half* __restrict__ dst, int n4) {
    int i = blockIdx.x * blockDim.x + threadIdx.x;
    if (i >= n4) return;
    float4 v = ((const float4*)src)[i];
    union { unsigned short u[4]; uint2 p; } pk;
    __half h0 = __float2half(v.x), h1 = __float2half(v.y);
    __half h2 = __float2half(v.z), h3 = __float2half(v.w);
    pk.u[0] = *(unsigned short*)&h0; pk.u[1] = *(unsigned short*)&h1;
    pk.u[2] = *(unsigned short*)&h2; pk.u[3] = *(unsigned short*)&h3;
    ((uint2*)dst)[i] = pk.p;
}

// fp32 -> fp16 hi/lo split (activations)
__global__ void split_kernel(const float* __restrict__ src,
                             __half* __restrict__ hi,
                             __half* __restrict__ lo, int n4) {
    int i = blockIdx.x * blockDim.x + threadIdx.x;
    if (i >= n4) return;
    float4 v = ((const float4*)src)[i];
    union { unsigned short u[4]; uint2 p; } ph, pl;
    float vv[4] = {v.x, v.y, v.z, v.w};
#pragma unroll
    for (int j = 0; j < 4; j++) {
        __half h = __float2half(vv[j]);
        __half l = __float2half(vv[j] - __half2float(h));
        ph.u[j] = *(unsigned short*)&h;
        pl.u[j] = *(unsigned short*)&l;
    }
    ((uint2*)hi)[i] = ph.p;
    ((uint2*)lo)[i] = pl.p;
}

__global__ void gating_kernel(const float* __restrict__ x,
                              const float* __restrict__ noise,
                              const float* __restrict__ gate_w,
                              const float* __restrict__ gate_b,
                              const float* __restrict__ noise_w,
                              const float* __restrict__ noise_b,
                              float* __restrict__ w_out) {
    int warp = blockIdx.x * (blockDim.x >> 5) + (threadIdx.x >> 5);
    int lane = threadIdx.x & 31;
    if (warp >= T) return;
    const float* xr = x + (size_t)warp * DIN;

    float ag[NE], an[NE];
#pragma unroll
    for (int e = 0; e < NE; e++) { ag[e] = 0.f; an[e] = 0.f; }
    for (int ii = 0; ii < DIN / 32; ii++) {
        int i = ii * 32 + lane;
        float xv = xr[i];
        float4 g0 = *(const float4*)(gate_w + (size_t)i * NE);
        float4 g1 = *(const float4*)(gate_w + (size_t)i * NE + 4);
        float4 n0 = *(const float4*)(noise_w + (size_t)i * NE);
        float4 n1 = *(const float4*)(noise_w + (size_t)i * NE + 4);
        ag[0] = fmaf(xv, g0.x, ag[0]); ag[1] = fmaf(xv, g0.y, ag[1]);
        ag[2] = fmaf(xv, g0.z, ag[2]); ag[3] = fmaf(xv, g0.w, ag[3]);
        ag[4] = fmaf(xv, g1.x, ag[4]); ag[5] = fmaf(xv, g1.y, ag[5]);
        ag[6] = fmaf(xv, g1.z, ag[6]); ag[7] = fmaf(xv, g1.w, ag[7]);
        an[0] = fmaf(xv, n0.x, an[0]); an[1] = fmaf(xv, n0.y, an[1]);
        an[2] = fmaf(xv, n0.z, an[2]); an[3] = fmaf(xv, n0.w, an[3]);
        an[4] = fmaf(xv, n1.x, an[4]); an[5] = fmaf(xv, n1.y, an[5]);
        an[6] = fmaf(xv, n1.z, an[6]); an[7] = fmaf(xv, n1.w, an[7]);
    }
#pragma unroll
    for (int e = 0; e < NE; e++) {
#pragma unroll
        for (int o = 16; o > 0; o >>= 1) {
            ag[e] += __shfl_xor_sync(0xffffffffu, ag[e], o);
            an[e] += __shfl_xor_sync(0xffffffffu, an[e], o);
        }
    }
    if (lane == 0) {
        float l[NE];
#pragma unroll
        for (int e = 0; e < NE; e++) {
            float z = an[e] + noise_b[e];
            float sp = (z > 20.f) ? z : log1pf(expf(z));
            l[e] = ag[e] + gate_b[e] + noise[(size_t)warp * NE + e] * sp;
        }
        int i0 = 0; float v0 = l[0];
#pragma unroll
        for (int e = 1; e < NE; e++) if (l[e] > v0) { v0 = l[e]; i0 = e; }
        int i1 = -1; float v1 = -INFINITY;
#pragma unroll
        for (int e = 0; e < NE; e++) if (e != i0 && l[e] > v1) { v1 = l[e]; i1 = e; }
        float eb = expf(v1 - v0);
        float w0 = 1.f / (1.f + eb);
        float w1 = eb / (1.f + eb);
        float wrow[NE];
#pragma unroll
        for (int e = 0; e < NE; e++) wrow[e] = 0.f;
        wrow[i0] = w0; wrow[i1] = w1;
#pragma unroll
        for (int e = 0; e < NE; e++) w_out[(size_t)warp * NE + e] = wrow[e];
        int p0 = atomicAdd(&g_count[i0], 1);
        int p1 = atomicAdd(&g_count[i1], 1);
        g_tokens[i0 * T + p0] = warp;
        g_tokens[i1 * T + p1] = warp;
        g_tok_e[2 * warp]     = i0; g_tok_pos[2 * warp]     = p0; g_tok_w[2 * warp]     = w0;
        g_tok_e[2 * warp + 1] = i1; g_tok_pos[2 * warp + 1] = p1; g_tok_w[2 * warp + 1] = w1;
    }
}

__global__ void offsets_kernel() {
    if (threadIdx.x == 0) {
        int s = 0;
        for (int e = 0; e < NE; e++) { g_offset[e] = s; s += g_count[e]; }
    }
}

// ---------------------------------------------------------------- mma.sync GEMM
// 128x256x64 tiles, 8 warps (2x4, 64x64). A = activation hi/lo fp16 (exact split),
// B = weights single fp16 (native [k][n], via ldmatrix.trans). 2 passes:
// acc += A_hi*B; acc += A_lo*B. 3-stage cp.async pipeline.
template <int PHASE>
__global__ __launch_bounds__(256, 1) void gemm_mma_kernel(const float* __restrict__ bias) {
    constexpr int KD = (PHASE == 1) ? DIN : HID;
    constexpr int ND = (PHASE == 1) ? HID : DOUT;
    constexpr int NT = ND / BN;
    constexpr int NK = KD / BK;
    constexpr bool GATHER = (PHASE == 1);

    int e = blockIdx.x / NT, nt = blockIdx.x % NT;
    int mt = blockIdx.y;
    int cnt = g_count[e];
    int m0 = mt * BM;
    if (m0 >= cnt) return;
    int n0 = nt * BN;
    int base = g_offset[e];
    size_t arow0 = (size_t)(base + m0);

    extern __shared__ char smem[];
    int* toks = (int*)smem;                    // 128 ints
    float* sbias = (float*)(smem + 1024);      // 256 floats
    uint32_t stgu = smem_to_u32(smem) + 2048;

    int tid = threadIdx.x, wid = tid >> 5, lane = tid & 31;
    int warp_m = wid >> 2, warp_n = wid & 3;

    if (GATHER && tid < BM) {
        int rr = m0 + tid;
        toks[tid] = (rr < cnt) ? g_tokens[e * T + rr] : -1;
    }
    sbias[tid] = bias[(size_t)e * ND + n0 + tid];
    __syncthreads();

    const __half* Ahi = (PHASE == 1) ? g_xhi : g_hhi;
    const __half* Alo = (PHASE == 1) ? g_xlo : g_hlo;
    const __half* B   = (PHASE == 1) ? g_w1  : g_w2;

    // A side: thread -> row r = tid>>1, chunks (tid&1)*4 + j (j<4)
    int ar = tid >> 1, asub = tid & 1;
    uint32_t aszA;
    const __half *aPhi, *aPlo;
    {
        bool valid; size_t srow;
        if (GATHER) { int tk = toks[ar]; valid = (tk >= 0); srow = (size_t)(valid ? tk : 0); }
        else        { valid = (m0 + ar) < cnt; srow = arow0 + (valid ? ar : 0); }
        aszA = valid ? 16u : 0u;
        aPhi = Ahi + srow * KD + asub * 32;
        aPlo = Alo + srow * KD + asub * 32;
    }
    uint32_t sdA[4];
#pragma unroll
    for (int j = 0; j < 4; j++)
        sdA[j] = SWZ_A((uint32_t)(ar * 128 + (asub * 4 + j) * 16));

    // B side: thread -> k-row kb = tid>>5 (+8j), chunk c = tid&31
    int kb = tid >> 5, bc = tid & 31;
    const __half* bP = B + ((size_t)e * KD + kb) * ND + n0 + bc * 8;
    uint32_t sdB[8];
#pragma unroll
    for (int j = 0; j < 8; j++)
        sdB[j] = SWZ_B((uint32_t)((kb + 8 * j) * 512 + bc * 16));

    auto issue = [&](int ck) {
        uint32_t st = stgu + (uint32_t)((ck % NSTAGE) * STG_BYTES);
        size_t koA = (size_t)ck * BK;
        size_t koB = (size_t)ck * BK * ND;
#pragma unroll
        for (int j = 0; j < 4; j++) {
            cp_async16(st + SM_AHI + sdA[j], aPhi + koA + j * 8, aszA);
            cp_async16(st + SM_ALO + sdA[j], aPlo + koA + j * 8, aszA);
        }
#pragma unroll
        for (int j = 0; j < 8; j++)
            cp_async16(st + SM_B + sdB[j], bP + koB + (size_t)(8 * j) * ND, 16u);
    };

    float acc[4][8][4];
#pragma unroll
    for (int a = 0; a < 4; a++)
#pragma unroll
        for (int b = 0; b < 8; b++)
#pragma unroll
            for (int r = 0; r < 4; r++) acc[a][b][r] = 0.f;

    issue(0); CP_COMMIT();
    issue(1); CP_COMMIT();

    for (int ck = 0; ck < NK; ck++) {
        CP_WAIT(1);
        __syncthreads();
        if (ck + 2 < NK) issue(ck + 2);
        CP_COMMIT();

        uint32_t sbase = stgu + (uint32_t)((ck % NSTAGE) * STG_BYTES);
#pragma unroll
        for (int ks = 0; ks < 4; ks++) {
            uint32_t bf[16];
#pragma unroll
            for (int p = 0; p < 4; p++) {
                uint32_t bo = SWZ_B((uint32_t)((ks * 16 + (lane & 15)) * 512 +
                                               warp_n * 128 + p * 32 + (lane >> 4) * 16));
                ldmx4t(&bf[p * 4], sbase + SM_B + bo);
            }
#pragma unroll
            for (int fm = 0; fm < 4; fm++) {
                uint32_t ao = SWZ_A((uint32_t)((warp_m * 64 + fm * 16 + (lane & 15)) * 128 +
                                               ks * 32 + (lane >> 4) * 16));
                uint32_t ah[4], al[4];
                ldmx4(ah, sbase + SM_AHI + ao);
                ldmx4(al, sbase + SM_ALO + ao);
#pragma unroll
                for (int fn = 0; fn < 8; fn++) {
                    uint32_t b0 = bf[fn * 2], b1 = bf[fn * 2 + 1];
                    mma_f16(acc[fm][fn], ah, b0, b1);
                    mma_f16(acc[fm][fn], al, b0, b1);
                }
            }
        }
    }

    // ---------------- epilogue ----------------
#pragma unroll
    for (int fm = 0; fm < 4; fm++) {
#pragma unroll
        for (int fn = 0; fn < 8; fn++) {
            int col = warp_n * 64 + fn * 8 + (lane & 3) * 2;
            float bv0 = sbias[col], bv1 = sbias[col + 1];
#pragma unroll
            for (int h = 0; h < 2; h++) {
                int row = warp_m * 64 + fm * 16 + (lane >> 2) + h * 8;
                if (m0 + row >= cnt) continue;
                size_t crow = arow0 + row;
                float v0 = acc[fm][fn][h * 2 + 0] + bv0;
                float v1 = acc[fm][fn][h * 2 + 1] + bv1;
                if (PHASE == 1) {
                    v0 = fmaxf(v0, 0.f); v1 = fmaxf(v1, 0.f);
                    __half h0 = __float2half(v0);
                    __half h1 = __float2half(v1);
                    __half l0 = __float2half(v0 - __half2float(h0));
                    __half l1 = __float2half(v1 - __half2float(h1));
                    union { unsigned short u[2]; uint32_t w; } ph, pl;
                    ph.u[0] = *(unsigned short*)&h0; ph.u[1] = *(unsigned short*)&h1;
                    pl.u[0] = *(unsigned short*)&l0; pl.u[1] = *(unsigned short*)&l1;
                    size_t o = crow * (size_t)ND + n0 + col;
                    *(uint32_t*)(g_hhi + o) = ph.w;
                    *(uint32_t*)(g_hlo + o) = pl.w;
                } else {
                    float2 v; v.x = v0; v.y = v1;
                    *(float2*)(g_O + crow * (size_t)ND + n0 + col) = v;
                }
            }
        }
    }
}

// ---------------------------------------------------------------- combine
__global__ void combine_kernel(float* __restrict__ out) {
    int t = blockIdx.x;
    int e0 = g_tok_e[2 * t], e1 = g_tok_e[2 * t + 1];
    int r0 = g_offset[e0] + g_tok_pos[2 * t];
    int r1 = g_offset[e1] + g_tok_pos[2 * t + 1];
    float w0 = g_tok_w[2 * t], w1 = g_tok_w[2 * t + 1];
    const float4* a = (const float4*)(g_O + (size_t)r0 * DOUT);
    const float4* b = (const float4*)(g_O + (size_t)r1 * DOUT);
    float4* o = (float4*)(out + (size_t)t * DOUT);
    for (int i = threadIdx.x; i < DOUT / 4; i += blockDim.x) {
        float4 av = a[i], bv = b[i];
        float4 r;
        r.x = w0 * av.x + w1 * bv.x;
        r.y = w0 * av.y + w1 * bv.y;
        r.z = w0 * av.z + w1 * bv.z;
        r.w = w0 * av.w + w1 * bv.w;
        o[i] = r;
    }
}

// ---------------------------------------------------------------- launch
extern "C" void kernel_launch(void* const* d_in, const int* in_sizes, int n_in,
                              void* d_out, int out_size) {
    const float* x       = (const float*)d_in[0];
    const float* noise   = (const float*)d_in[1];
    const float* gate_w  = (const float*)d_in[2];
    const float* gate_b  = (const float*)d_in[3];
    const float* noise_w = (const float*)d_in[4];
    const float* noise_b = (const float*)d_in[5];
    const float* w1      = (const float*)d_in[6];
    const float* b1      = (const float*)d_in[7];
    const float* w2      = (const float*)d_in[8];
    const float* b2      = (const float*)d_in[9];
    float* out = (float*)d_out;

    float* w_out;
    if (out_size >= T * DOUT + T * NE) {
        w_out = out + (size_t)T * DOUT;
    } else {
        cudaGetSymbolAddress((void**)&w_out, g_wdummy);
    }

    cudaFuncSetAttribute(gemm_mma_kernel<1>, cudaFuncAttributeMaxDynamicSharedMemorySize, SMEM_TOT);
    cudaFuncSetAttribute(gemm_mma_kernel<2>, cudaFuncAttributeMaxDynamicSharedMemorySize, SMEM_TOT);

    __half *xhi, *xlo, *w1h, *w2h;
    cudaGetSymbolAddress((void**)&xhi, g_xhi);
    cudaGetSymbolAddress((void**)&xlo, g_xlo);
    cudaGetSymbolAddress((void**)&w1h, g_w1);
    cudaGetSymbolAddress((void**)&w2h, g_w2);

    zero_counts_kernel<<<1, 32>>>();
    split_kernel<<<(T * DIN / 4 + 255) / 256, 256>>>(x, xhi, xlo, T * DIN / 4);
    conv_kernel<<<(NE * DIN * HID / 4 + 255) / 256, 256>>>(w1, w1h, NE * DIN * HID / 4);
    conv_kernel<<<(NE * HID * DOUT / 4 + 255) / 256, 256>>>(w2, w2h, NE * HID * DOUT / 4);
    gating_kernel<<<T / 4, 128>>>(x, noise, gate_w, gate_b, noise_w, noise_b, w_out);
    offsets_kernel<<<1, 32>>>();
    gemm_mma_kernel<1><<<dim3(NE * (HID / BN), MT), 256, SMEM_TOT>>>(b1);
    gemm_mma_kernel<2><<<dim3(NE * (DOUT / BN), MT), 256, SMEM_TOT>>>(b2);
    combine_kernel<<<T, 256>>>(out);
}

// round 7
// speedup vs baseline: 6.6833x; 1.6868x over previous
#include <cuda_runtime.h>
#include <cuda_fp16.h>
#include <math.h>
#include <stdint.h>

#define T      4096
#define DIN    1024
#define DOUT   1024
#define NE     8
#define HID    4096
#define BM     128
#define BN     256
#define BK     64
#define MT     32

// smem stage: A 128x128B (16KB), B 64x512B (32KB)
#define SM_A   0
#define SM_B   16384
#define STG_BYTES 49152
#define NSTAGE 4
#define SMEM_TOT (2048 + NSTAGE * STG_BYTES)   // 198656

// ---------------------------------------------------------------- helpers
__device__ __forceinline__ uint32_t smem_to_u32(const void* p) {
    uint32_t a;
    asm("{ .reg .u64 t; cvta.to.shared.u64 t, %1; cvt.u32.u64 %0, t; }" : "=r"(a) : "l"(p));
    return a;
}
__device__ __forceinline__ void ldmx4(uint32_t* r, uint32_t addr) {
    asm volatile("ldmatrix.sync.aligned.m8n8.x4.shared.b16 {%0,%1,%2,%3}, [%4];"
                 : "=r"(r[0]), "=r"(r[1]), "=r"(r[2]), "=r"(r[3]) : "r"(addr));
}
__device__ __forceinline__ void ldmx4t(uint32_t* r, uint32_t addr) {
    asm volatile("ldmatrix.sync.aligned.m8n8.x4.trans.shared.b16 {%0,%1,%2,%3}, [%4];"
                 : "=r"(r[0]), "=r"(r[1]), "=r"(r[2]), "=r"(r[3]) : "r"(addr));
}
__device__ __forceinline__ void mma_f16(float* c, const uint32_t* a, uint32_t b0, uint32_t b1) {
    asm volatile("mma.sync.aligned.m16n8k16.row.col.f32.f16.f16.f32 "
                 "{%0,%1,%2,%3}, {%4,%5,%6,%7}, {%8,%9}, {%0,%1,%2,%3};"
                 : "+f"(c[0]), "+f"(c[1]), "+f"(c[2]), "+f"(c[3])
                 : "r"(a[0]), "r"(a[1]), "r"(a[2]), "r"(a[3]), "r"(b0), "r"(b1));
}
__device__ __forceinline__ void cp_async16(uint32_t dst, const void* src, uint32_t sz) {
    asm volatile("cp.async.cg.shared.global [%0], [%1], 16, %2;"
                 :: "r"(dst), "l"(src), "r"(sz));
}
#define CP_COMMIT() asm volatile("cp.async.commit_group;")
#define CP_WAIT(n)  asm volatile("cp.async.wait_group %0;" :: "n"(n))
#define SWZ_A(o) ((o) ^ (((o) >> 3) & 0x70))   // 128B rows
#define SWZ_B(o) ((o) ^ (((o) >> 5) & 0x70))   // 512B rows

// ---------------------------------------------------------------- device state
__device__ int   g_count[NE];
__device__ int   g_offset[NE];
__device__ int   g_tokens[NE * T];
__device__ int   g_tok_e[T * 2];
__device__ int   g_tok_pos[T * 2];
__device__ float g_tok_w[T * 2];
__device__ __align__(16) __half g_xh[(size_t)T * DIN];
__device__ __align__(16) __half g_w1[(size_t)NE * DIN * HID];   // native [e][k][n]
__device__ __align__(16) __half g_w2[(size_t)NE * HID * DOUT];  // native [e][k][n]
__device__ __align__(16) __half g_h[(size_t)T * 2 * HID];
__device__ __align__(16) float g_O[(size_t)T * 2 * DOUT];
__device__ float g_wdummy[T * NE];

// ---------------------------------------------------------------- small kernels
__global__ void zero_counts_kernel() {
    if (threadIdx.x < NE) g_count[threadIdx.x] = 0;
}

// fp32 -> fp16 convert
__global__ void conv_kernel(const float* __restrict__ src, __half* __restrict__ dst, int n4) {
    int i = blockIdx.x * blockDim.x + threadIdx.x;
    if (i >= n4) return;
    float4 v = ((const float4*)src)[i];
    union { unsigned short u[4]; uint2 p; } pk;
    __half h0 = __float2half(v.x), h1 = __float2half(v.y);
    __half h2 = __float2half(v.z), h3 = __float2half(v.w);
    pk.u[0] = *(unsigned short*)&h0; pk.u[1] = *(unsigned short*)&h1;
    pk.u[2] = *(unsigned short*)&h2; pk.u[3] = *(unsigned short*)&h3;
    ((uint2*)dst)[i] = pk.p;
}

__global__ void gating_kernel(const float* __restrict__ x,
                              const float* __restrict__ noise,
                              const float* __restrict__ gate_w,
                              const float* __restrict__ gate_b,
                              const float* __restrict__ noise_w,
                              const float* __restrict__ noise_b,
                              float* __restrict__ w_out) {
    int warp = blockIdx.x * (blockDim.x >> 5) + (threadIdx.x >> 5);
    int lane = threadIdx.x & 31;
    if (warp >= T) return;
    const float* xr = x + (size_t)warp * DIN;

    float ag[NE], an[NE];
#pragma unroll
    for (int e = 0; e < NE; e++) { ag[e] = 0.f; an[e] = 0.f; }
    for (int ii = 0; ii < DIN / 32; ii++) {
        int i = ii * 32 + lane;
        float xv = xr[i];
        float4 g0 = *(const float4*)(gate_w + (size_t)i * NE);
        float4 g1 = *(const float4*)(gate_w + (size_t)i * NE + 4);
        float4 n0 = *(const float4*)(noise_w + (size_t)i * NE);
        float4 n1 = *(const float4*)(noise_w + (size_t)i * NE + 4);
        ag[0] = fmaf(xv, g0.x, ag[0]); ag[1] = fmaf(xv, g0.y, ag[1]);
        ag[2] = fmaf(xv, g0.z, ag[2]); ag[3] = fmaf(xv, g0.w, ag[3]);
        ag[4] = fmaf(xv, g1.x, ag[4]); ag[5] = fmaf(xv, g1.y, ag[5]);
        ag[6] = fmaf(xv, g1.z, ag[6]); ag[7] = fmaf(xv, g1.w, ag[7]);
        an[0] = fmaf(xv, n0.x, an[0]); an[1] = fmaf(xv, n0.y, an[1]);
        an[2] = fmaf(xv, n0.z, an[2]); an[3] = fmaf(xv, n0.w, an[3]);
        an[4] = fmaf(xv, n1.x, an[4]); an[5] = fmaf(xv, n1.y, an[5]);
        an[6] = fmaf(xv, n1.z, an[6]); an[7] = fmaf(xv, n1.w, an[7]);
    }
#pragma unroll
    for (int e = 0; e < NE; e++) {
#pragma unroll
        for (int o = 16; o > 0; o >>= 1) {
            ag[e] += __shfl_xor_sync(0xffffffffu, ag[e], o);
            an[e] += __shfl_xor_sync(0xffffffffu, an[e], o);
        }
    }
    if (lane == 0) {
        float l[NE];
#pragma unroll
        for (int e = 0; e < NE; e++) {
            float z = an[e] + noise_b[e];
            float sp = (z > 20.f) ? z : log1pf(expf(z));
            l[e] = ag[e] + gate_b[e] + noise[(size_t)warp * NE + e] * sp;
        }
        int i0 = 0; float v0 = l[0];
#pragma unroll
        for (int e = 1; e < NE; e++) if (l[e] > v0) { v0 = l[e]; i0 = e; }
        int i1 = -1; float v1 = -INFINITY;
#pragma unroll
        for (int e = 0; e < NE; e++) if (e != i0 && l[e] > v1) { v1 = l[e]; i1 = e; }
        float eb = expf(v1 - v0);
        float w0 = 1.f / (1.f + eb);
        float w1 = eb / (1.f + eb);
        float wrow[NE];
#pragma unroll
        for (int e = 0; e < NE; e++) wrow[e] = 0.f;
        wrow[i0] = w0; wrow[i1] = w1;
#pragma unroll
        for (int e = 0; e < NE; e++) w_out[(size_t)warp * NE + e] = wrow[e];
        int p0 = atomicAdd(&g_count[i0], 1);
        int p1 = atomicAdd(&g_count[i1], 1);
        g_tokens[i0 * T + p0] = warp;
        g_tokens[i1 * T + p1] = warp;
        g_tok_e[2 * warp]     = i0; g_tok_pos[2 * warp]     = p0; g_tok_w[2 * warp]     = w0;
        g_tok_e[2 * warp + 1] = i1; g_tok_pos[2 * warp + 1] = p1; g_tok_w[2 * warp + 1] = w1;
    }
}

__global__ void offsets_kernel() {
    if (threadIdx.x == 0) {
        int s = 0;
        for (int e = 0; e < NE; e++) { g_offset[e] = s; s += g_count[e]; }
    }
}

// ---------------------------------------------------------------- mma.sync GEMM
// 128x256x64 tiles, 8 warps (2x4, 64x64). Single-pass fp16: A = act fp16,
// B = weights fp16 (native [k][n], via ldmatrix.trans). 4-stage cp.async.
template <int PHASE>
__global__ __launch_bounds__(256, 1) void gemm_mma_kernel(const float* __restrict__ bias) {
    constexpr int KD = (PHASE == 1) ? DIN : HID;
    constexpr int ND = (PHASE == 1) ? HID : DOUT;
    constexpr int NT = ND / BN;
    constexpr int NK = KD / BK;
    constexpr bool GATHER = (PHASE == 1);

    int e = blockIdx.x / NT, nt = blockIdx.x % NT;
    int mt = blockIdx.y;
    int cnt = g_count[e];
    int m0 = mt * BM;
    if (m0 >= cnt) return;
    int n0 = nt * BN;
    int base = g_offset[e];
    size_t arow0 = (size_t)(base + m0);

    extern __shared__ char smem[];
    int* toks = (int*)smem;                    // 128 ints
    float* sbias = (float*)(smem + 1024);      // 256 floats
    uint32_t stgu = smem_to_u32(smem) + 2048;

    int tid = threadIdx.x, wid = tid >> 5, lane = tid & 31;
    int warp_m = wid >> 2, warp_n = wid & 3;

    if (GATHER && tid < BM) {
        int rr = m0 + tid;
        toks[tid] = (rr < cnt) ? g_tokens[e * T + rr] : -1;
    }
    sbias[tid] = bias[(size_t)e * ND + n0 + tid];
    __syncthreads();

    const __half* A = (PHASE == 1) ? g_xh : g_h;
    const __half* B = (PHASE == 1) ? g_w1 : g_w2;

    // A side: 128 rows x 8 chunks = 1024 chunks, 256 threads x 4
    int ar = tid >> 1, asub = tid & 1;
    uint32_t aszA;
    const __half* aP;
    {
        bool valid; size_t srow;
        if (GATHER) { int tk = toks[ar]; valid = (tk >= 0); srow = (size_t)(valid ? tk : 0); }
        else        { valid = (m0 + ar) < cnt; srow = arow0 + (valid ? ar : 0); }
        aszA = valid ? 16u : 0u;
        aP = A + srow * KD + asub * 32;
    }
    uint32_t sdA[4];
#pragma unroll
    for (int j = 0; j < 4; j++)
        sdA[j] = SWZ_A((uint32_t)(ar * 128 + (asub * 4 + j) * 16));

    // B side: 64 k-rows x 32 chunks = 2048 chunks, 256 threads x 8
    int kb = tid >> 5, bc = tid & 31;
    const __half* bP = B + ((size_t)e * KD + kb) * ND + n0 + bc * 8;
    uint32_t sdB[8];
#pragma unroll
    for (int j = 0; j < 8; j++)
        sdB[j] = SWZ_B((uint32_t)((kb + 8 * j) * 512 + bc * 16));

    auto issue = [&](int ck) {
        uint32_t st = stgu + (uint32_t)((ck % NSTAGE) * STG_BYTES);
        size_t koA = (size_t)ck * BK;
        size_t koB = (size_t)ck * BK * ND;
#pragma unroll
        for (int j = 0; j < 4; j++)
            cp_async16(st + SM_A + sdA[j], aP + koA + j * 8, aszA);
#pragma unroll
        for (int j = 0; j < 8; j++)
            cp_async16(st + SM_B + sdB[j], bP + koB + (size_t)(8 * j) * ND, 16u);
    };

    float acc[4][8][4];
#pragma unroll
    for (int a = 0; a < 4; a++)
#pragma unroll
        for (int b = 0; b < 8; b++)
#pragma unroll
            for (int r = 0; r < 4; r++) acc[a][b][r] = 0.f;

    issue(0); CP_COMMIT();
    issue(1); CP_COMMIT();
    issue(2); CP_COMMIT();

    for (int ck = 0; ck < NK; ck++) {
        CP_WAIT(2);
        __syncthreads();
        if (ck + 3 < NK) issue(ck + 3);
        CP_COMMIT();

        uint32_t sbase = stgu + (uint32_t)((ck % NSTAGE) * STG_BYTES);
#pragma unroll
        for (int ks = 0; ks < 4; ks++) {
            uint32_t bf[16];
#pragma unroll
            for (int p = 0; p < 4; p++) {
                uint32_t bo = SWZ_B((uint32_t)((ks * 16 + (lane & 15)) * 512 +
                                               warp_n * 128 + p * 32 + (lane >> 4) * 16));
                ldmx4t(&bf[p * 4], sbase + SM_B + bo);
            }
#pragma unroll
            for (int fm = 0; fm < 4; fm++) {
                uint32_t ao = SWZ_A((uint32_t)((warp_m * 64 + fm * 16 + (lane & 15)) * 128 +
                                               ks * 32 + (lane >> 4) * 16));
                uint32_t af[4];
                ldmx4(af, sbase + SM_A + ao);
#pragma unroll
                for (int fn = 0; fn < 8; fn++)
                    mma_f16(acc[fm][fn], af, bf[fn * 2], bf[fn * 2 + 1]);
            }
        }
    }

    // ---------------- epilogue ----------------
#pragma unroll
    for (int fm = 0; fm < 4; fm++) {
#pragma unroll
        for (int fn = 0; fn < 8; fn++) {
            int col = warp_n * 64 + fn * 8 + (lane & 3) * 2;
            float bv0 = sbias[col], bv1 = sbias[col + 1];
#pragma unroll
            for (int h = 0; h < 2; h++) {
                int row = warp_m * 64 + fm * 16 + (lane >> 2) + h * 8;
                if (m0 + row >= cnt) continue;
                size_t crow = arow0 + row;
                float v0 = acc[fm][fn][h * 2 + 0] + bv0;
                float v1 = acc[fm][fn][h * 2 + 1] + bv1;
                if (PHASE == 1) {
                    v0 = fmaxf(v0, 0.f); v1 = fmaxf(v1, 0.f);
                    __half h0 = __float2half(v0);
                    __half h1 = __float2half(v1);
                    union { unsigned short u[2]; uint32_t w; } pk;
                    pk.u[0] = *(unsigned short*)&h0; pk.u[1] = *(unsigned short*)&h1;
                    *(uint32_t*)(g_h + crow * (size_t)ND + n0 + col) = pk.w;
                } else {
                    float2 v; v.x = v0; v.y = v1;
                    *(float2*)(g_O + crow * (size_t)ND + n0 + col) = v;
                }
            }
        }
    }
}

// ---------------------------------------------------------------- combine
__global__ void combine_kernel(float* __restrict__ out) {
    int t = blockIdx.x;
    int e0 = g_tok_e[2 * t], e1 = g_tok_e[2 * t + 1];
    int r0 = g_offset[e0] + g_tok_pos[2 * t];
    int r1 = g_offset[e1] + g_tok_pos[2 * t + 1];
    float w0 = g_tok_w[2 * t], w1 = g_tok_w[2 * t + 1];
    const float4* a = (const float4*)(g_O + (size_t)r0 * DOUT);
    const float4* b = (const float4*)(g_O + (size_t)r1 * DOUT);
    float4* o = (float4*)(out + (size_t)t * DOUT);
    for (int i = threadIdx.x; i < DOUT / 4; i += blockDim.x) {
        float4 av = a[i], bv = b[i];
        float4 r;
        r.x = w0 * av.x + w1 * bv.x;
        r.y = w0 * av.y + w1 * bv.y;
        r.z = w0 * av.z + w1 * bv.z;
        r.w = w0 * av.w + w1 * bv.w;
        o[i] = r;
    }
}

// ---------------------------------------------------------------- launch
extern "C" void kernel_launch(void* const* d_in, const int* in_sizes, int n_in,
                              void* d_out, int out_size) {
    const float* x       = (const float*)d_in[0];
    const float* noise   = (const float*)d_in[1];
    const float* gate_w  = (const float*)d_in[2];
    const float* gate_b  = (const float*)d_in[3];
    const float* noise_w = (const float*)d_in[4];
    const float* noise_b = (const float*)d_in[5];
    const float* w1      = (const float*)d_in[6];
    const float* b1      = (const float*)d_in[7];
    const float* w2      = (const float*)d_in[8];
    const float* b2      = (const float*)d_in[9];
    float* out = (float*)d_out;

    float* w_out;
    if (out_size >= T * DOUT + T * NE) {
        w_out = out + (size_t)T * DOUT;
    } else {
        cudaGetSymbolAddress((void**)&w_out, g_wdummy);
    }

    cudaFuncSetAttribute(gemm_mma_kernel<1>, cudaFuncAttributeMaxDynamicSharedMemorySize, SMEM_TOT);
    cudaFuncSetAttribute(gemm_mma_kernel<2>, cudaFuncAttributeMaxDynamicSharedMemorySize, SMEM_TOT);

    __half *xh, *w1h, *w2h;
    cudaGetSymbolAddress((void**)&xh, g_xh);
    cudaGetSymbolAddress((void**)&w1h, g_w1);
    cudaGetSymbolAddress((void**)&w2h, g_w2);

    zero_counts_kernel<<<1, 32>>>();
    conv_kernel<<<(T * DIN / 4 + 255) / 256, 256>>>(x, xh, T * DIN / 4);
    conv_kernel<<<(NE * DIN * HID / 4 + 255) / 256, 256>>>(w1, w1h, NE * DIN * HID / 4);
    conv_kernel<<<(NE * HID * DOUT / 4 + 255) / 256, 256>>>(w2, w2h, NE * HID * DOUT / 4);
    gating_kernel<<<T / 4, 128>>>(x, noise, gate_w, gate_b, noise_w, noise_b, w_out);
    offsets_kernel<<<1, 32>>>();
    gemm_mma_kernel<1><<<dim3(NE * (HID / BN), MT), 256, SMEM_TOT>>>(b1);
    gemm_mma_kernel<2><<<dim3(NE * (DOUT / BN), MT), 256, SMEM_TOT>>>(b2);
    combine_kernel<<<T, 256>>>(out);
}

// round 8
// speedup vs baseline: 7.1381x; 1.0681x over previous
#include <cuda_runtime.h>
#include <cuda_fp16.h>
#include <math.h>
#include <stdint.h>

#define T      4096
#define DIN    1024
#define DOUT   1024
#define NE     8
#define HID    4096
#define BM     128
#define BN     256
#define BK     64
#define MT     32
#define NTHR   512

// smem stage: A 128x128B (16KB), B 64x512B (32KB)
#define SM_A   0
#define SM_B   16384
#define STG_BYTES 49152
#define NSTAGE 4
#define SMEM_TOT (2048 + NSTAGE * STG_BYTES)   // 198656

// ---------------------------------------------------------------- helpers
__device__ __forceinline__ uint32_t smem_to_u32(const void* p) {
    uint32_t a;
    asm("{ .reg .u64 t; cvta.to.shared.u64 t, %1; cvt.u32.u64 %0, t; }" : "=r"(a) : "l"(p));
    return a;
}
__device__ __forceinline__ void ldmx4(uint32_t* r, uint32_t addr) {
    asm volatile("ldmatrix.sync.aligned.m8n8.x4.shared.b16 {%0,%1,%2,%3}, [%4];"
                 : "=r"(r[0]), "=r"(r[1]), "=r"(r[2]), "=r"(r[3]) : "r"(addr));
}
__device__ __forceinline__ void ldmx4t(uint32_t* r, uint32_t addr) {
    asm volatile("ldmatrix.sync.aligned.m8n8.x4.trans.shared.b16 {%0,%1,%2,%3}, [%4];"
                 : "=r"(r[0]), "=r"(r[1]), "=r"(r[2]), "=r"(r[3]) : "r"(addr));
}
__device__ __forceinline__ void mma_f16(float* c, const uint32_t* a, uint32_t b0, uint32_t b1) {
    asm volatile("mma.sync.aligned.m16n8k16.row.col.f32.f16.f16.f32 "
                 "{%0,%1,%2,%3}, {%4,%5,%6,%7}, {%8,%9}, {%0,%1,%2,%3};"
                 : "+f"(c[0]), "+f"(c[1]), "+f"(c[2]), "+f"(c[3])
                 : "r"(a[0]), "r"(a[1]), "r"(a[2]), "r"(a[3]), "r"(b0), "r"(b1));
}
__device__ __forceinline__ void cp_async16(uint32_t dst, const void* src, uint32_t sz) {
    asm volatile("cp.async.cg.shared.global [%0], [%1], 16, %2;"
                 :: "r"(dst), "l"(src), "r"(sz));
}
#define CP_COMMIT() asm volatile("cp.async.commit_group;")
#define CP_WAIT(n)  asm volatile("cp.async.wait_group %0;" :: "n"(n))
#define SWZ_A(o) ((o) ^ (((o) >> 3) & 0x70))   // 128B rows
#define SWZ_B(o) ((o) ^ (((o) >> 5) & 0x70))   // 512B rows

// ---------------------------------------------------------------- device state
__device__ int   g_count[NE];
__device__ int   g_offset[NE];
__device__ int   g_tokens[NE * T];
__device__ int   g_tok_e[T * 2];
__device__ int   g_tok_pos[T * 2];
__device__ float g_tok_w[T * 2];
__device__ __align__(16) __half g_xh[(size_t)T * DIN];
__device__ __align__(16) __half g_w1[(size_t)NE * DIN * HID];   // native [e][k][n]
__device__ __align__(16) __half g_w2[(size_t)NE * HID * DOUT];  // native [e][k][n]
__device__ __align__(16) __half g_h[(size_t)T * 2 * HID];
__device__ __align__(16) float g_O[(size_t)T * 2 * DOUT];
__device__ float g_wdummy[T * NE];

// ---------------------------------------------------------------- small kernels
__global__ void zero_counts_kernel() {
    if (threadIdx.x < NE) g_count[threadIdx.x] = 0;
}

// fp32 -> fp16 convert, 8 elems/thread (16B stores)
__global__ void conv_kernel(const float* __restrict__ src, __half* __restrict__ dst, int n8) {
    int i = blockIdx.x * blockDim.x + threadIdx.x;
    if (i >= n8) return;
    float4 a = ((const float4*)src)[2 * i];
    float4 b = ((const float4*)src)[2 * i + 1];
    union { unsigned short u[8]; uint4 p; } pk;
    __half h0 = __float2half(a.x), h1 = __float2half(a.y);
    __half h2 = __float2half(a.z), h3 = __float2half(a.w);
    __half h4 = __float2half(b.x), h5 = __float2half(b.y);
    __half h6 = __float2half(b.z), h7 = __float2half(b.w);
    pk.u[0] = *(unsigned short*)&h0; pk.u[1] = *(unsigned short*)&h1;
    pk.u[2] = *(unsigned short*)&h2; pk.u[3] = *(unsigned short*)&h3;
    pk.u[4] = *(unsigned short*)&h4; pk.u[5] = *(unsigned short*)&h5;
    pk.u[6] = *(unsigned short*)&h6; pk.u[7] = *(unsigned short*)&h7;
    ((uint4*)dst)[i] = pk.p;
}

// 512 threads = 16 warps = 16 tokens per block; two-phase bucket assignment.
__global__ __launch_bounds__(512) void gating_kernel(
        const float* __restrict__ x,
        const float* __restrict__ noise,
        const float* __restrict__ gate_w,
        const float* __restrict__ gate_b,
        const float* __restrict__ noise_w,
        const float* __restrict__ noise_b,
        float* __restrict__ w_out) {
    __shared__ int   si0[16], si1[16];
    __shared__ float sw0[16], sw1[16];
    __shared__ int   sp0[16], sp1[16];

    int wid = threadIdx.x >> 5, lane = threadIdx.x & 31;
    int tok = blockIdx.x * 16 + wid;
    const float* xr = x + (size_t)tok * DIN;

    float ag[NE], an[NE];
#pragma unroll
    for (int e = 0; e < NE; e++) { ag[e] = 0.f; an[e] = 0.f; }
    for (int ii = 0; ii < DIN / 32; ii++) {
        int i = ii * 32 + lane;
        float xv = xr[i];
        float4 g0 = *(const float4*)(gate_w + (size_t)i * NE);
        float4 g1 = *(const float4*)(gate_w + (size_t)i * NE + 4);
        float4 n0 = *(const float4*)(noise_w + (size_t)i * NE);
        float4 n1 = *(const float4*)(noise_w + (size_t)i * NE + 4);
        ag[0] = fmaf(xv, g0.x, ag[0]); ag[1] = fmaf(xv, g0.y, ag[1]);
        ag[2] = fmaf(xv, g0.z, ag[2]); ag[3] = fmaf(xv, g0.w, ag[3]);
        ag[4] = fmaf(xv, g1.x, ag[4]); ag[5] = fmaf(xv, g1.y, ag[5]);
        ag[6] = fmaf(xv, g1.z, ag[6]); ag[7] = fmaf(xv, g1.w, ag[7]);
        an[0] = fmaf(xv, n0.x, an[0]); an[1] = fmaf(xv, n0.y, an[1]);
        an[2] = fmaf(xv, n0.z, an[2]); an[3] = fmaf(xv, n0.w, an[3]);
        an[4] = fmaf(xv, n1.x, an[4]); an[5] = fmaf(xv, n1.y, an[5]);
        an[6] = fmaf(xv, n1.z, an[6]); an[7] = fmaf(xv, n1.w, an[7]);
    }
#pragma unroll
    for (int e = 0; e < NE; e++) {
#pragma unroll
        for (int o = 16; o > 0; o >>= 1) {
            ag[e] += __shfl_xor_sync(0xffffffffu, ag[e], o);
            an[e] += __shfl_xor_sync(0xffffffffu, an[e], o);
        }
    }
    if (lane == 0) {
        float l[NE];
#pragma unroll
        for (int e = 0; e < NE; e++) {
            float z = an[e] + noise_b[e];
            float sp = (z > 20.f) ? z : log1pf(expf(z));
            l[e] = ag[e] + gate_b[e] + noise[(size_t)tok * NE + e] * sp;
        }
        int i0 = 0; float v0 = l[0];
#pragma unroll
        for (int e = 1; e < NE; e++) if (l[e] > v0) { v0 = l[e]; i0 = e; }
        int i1 = -1; float v1 = -INFINITY;
#pragma unroll
        for (int e = 0; e < NE; e++) if (e != i0 && l[e] > v1) { v1 = l[e]; i1 = e; }
        float eb = expf(v1 - v0);
        float w0 = 1.f / (1.f + eb);
        float w1 = eb / (1.f + eb);
        float wrow[NE];
#pragma unroll
        for (int e = 0; e < NE; e++) wrow[e] = 0.f;
        wrow[i0] = w0; wrow[i1] = w1;
#pragma unroll
        for (int e = 0; e < NE; e++) w_out[(size_t)tok * NE + e] = wrow[e];
        si0[wid] = i0; si1[wid] = i1; sw0[wid] = w0; sw1[wid] = w1;
    }
    __syncthreads();
    // phase 2: one thread per expert assigns positions; one global atomic each
    if (threadIdx.x < NE) {
        int e = threadIdx.x;
        int c = 0;
        for (int tk = 0; tk < 16; tk++) {
            if (si0[tk] == e) sp0[tk] = c++;
            if (si1[tk] == e) sp1[tk] = c++;
        }
        if (c > 0) {
            int bse = atomicAdd(&g_count[e], c);
            for (int tk = 0; tk < 16; tk++) {
                int t2 = blockIdx.x * 16 + tk;
                if (si0[tk] == e) {
                    int p = bse + sp0[tk];
                    g_tokens[e * T + p] = t2;
                    g_tok_e[2 * t2] = e; g_tok_pos[2 * t2] = p; g_tok_w[2 * t2] = sw0[tk];
                }
                if (si1[tk] == e) {
                    int p = bse + sp1[tk];
                    g_tokens[e * T + p] = t2;
                    g_tok_e[2 * t2 + 1] = e; g_tok_pos[2 * t2 + 1] = p; g_tok_w[2 * t2 + 1] = sw1[tk];
                }
            }
        }
    }
}

__global__ void offsets_kernel() {
    if (threadIdx.x == 0) {
        int s = 0;
        for (int e = 0; e < NE; e++) { g_offset[e] = s; s += g_count[e]; }
    }
}

// ---------------------------------------------------------------- mma.sync GEMM
// 128x256x64 tiles, 16 warps (4x4 grid, warp tile 32x64). Single-pass fp16.
// A [m][k] K-major; B native [k][n] via ldmatrix.trans. 4-stage cp.async.
template <int PHASE>
__global__ __launch_bounds__(NTHR, 1) void gemm_mma_kernel(const float* __restrict__ bias) {
    constexpr int KD = (PHASE == 1) ? DIN : HID;
    constexpr int ND = (PHASE == 1) ? HID : DOUT;
    constexpr int NT = ND / BN;
    constexpr int NK = KD / BK;
    constexpr bool GATHER = (PHASE == 1);

    int e = blockIdx.x / NT, nt = blockIdx.x % NT;
    int mt = blockIdx.y;
    int cnt = g_count[e];
    int m0 = mt * BM;
    if (m0 >= cnt) return;
    int n0 = nt * BN;
    int base = g_offset[e];
    size_t arow0 = (size_t)(base + m0);

    extern __shared__ char smem[];
    int* toks = (int*)smem;                    // 128 ints
    float* sbias = (float*)(smem + 1024);      // 256 floats
    uint32_t stgu = smem_to_u32(smem) + 2048;

    int tid = threadIdx.x, wid = tid >> 5, lane = tid & 31;
    int warp_m = wid >> 2, warp_n = wid & 3;

    if (GATHER && tid < BM) {
        int rr = m0 + tid;
        toks[tid] = (rr < cnt) ? g_tokens[e * T + rr] : -1;
    }
    if (tid < BN) sbias[tid] = bias[(size_t)e * ND + n0 + tid];
    __syncthreads();

    const __half* A = (PHASE == 1) ? g_xh : g_h;
    const __half* B = (PHASE == 1) ? g_w1 : g_w2;

    // A side: 128 rows x 8 chunks = 1024 chunks; 512 threads x 2
    int ar = tid >> 2, ac = tid & 3;
    uint32_t aszA;
    const __half* aP;
    {
        bool valid; size_t srow;
        if (GATHER) { int tk = toks[ar]; valid = (tk >= 0); srow = (size_t)(valid ? tk : 0); }
        else        { valid = (m0 + ar) < cnt; srow = arow0 + (valid ? ar : 0); }
        aszA = valid ? 16u : 0u;
        aP = A + srow * KD + ac * 8;
    }
    uint32_t sdA[2];
#pragma unroll
    for (int j = 0; j < 2; j++)
        sdA[j] = SWZ_A((uint32_t)(ar * 128 + (ac + 4 * j) * 16));

    // B side: 64 k-rows x 32 chunks = 2048 chunks; 512 threads x 4
    int kb = tid >> 3, bc = tid & 7;
    const __half* bP = B + ((size_t)e * KD + kb) * ND + n0 + bc * 8;
    uint32_t sdB[4];
#pragma unroll
    for (int j = 0; j < 4; j++)
        sdB[j] = SWZ_B((uint32_t)(kb * 512 + (bc + 8 * j) * 16));

    auto issue = [&](int ck) {
        uint32_t st = stgu + (uint32_t)((ck % NSTAGE) * STG_BYTES);
        size_t koA = (size_t)ck * BK;
        size_t koB = (size_t)ck * BK * ND;
#pragma unroll
        for (int j = 0; j < 2; j++)
            cp_async16(st + SM_A + sdA[j], aP + koA + j * 32, aszA);
#pragma unroll
        for (int j = 0; j < 4; j++)
            cp_async16(st + SM_B + sdB[j], bP + koB + j * 64, 16u);
    };

    float acc[2][8][4];
#pragma unroll
    for (int a = 0; a < 2; a++)
#pragma unroll
        for (int b = 0; b < 8; b++)
#pragma unroll
            for (int r = 0; r < 4; r++) acc[a][b][r] = 0.f;

    issue(0); CP_COMMIT();
    issue(1); CP_COMMIT();
    issue(2); CP_COMMIT();

    for (int ck = 0; ck < NK; ck++) {
        CP_WAIT(2);
        __syncthreads();
        if (ck + 3 < NK) issue(ck + 3);
        CP_COMMIT();

        uint32_t sbase = stgu + (uint32_t)((ck % NSTAGE) * STG_BYTES);
#pragma unroll
        for (int ks = 0; ks < 4; ks++) {
            uint32_t bf[16];
#pragma unroll
            for (int p = 0; p < 4; p++) {
                uint32_t bo = SWZ_B((uint32_t)((ks * 16 + (lane & 15)) * 512 +
                                               warp_n * 128 + p * 32 + (lane >> 4) * 16));
                ldmx4t(&bf[p * 4], sbase + SM_B + bo);
            }
#pragma unroll
            for (int fm = 0; fm < 2; fm++) {
                uint32_t ao = SWZ_A((uint32_t)((warp_m * 32 + fm * 16 + (lane & 15)) * 128 +
                                               ks * 32 + (lane >> 4) * 16));
                uint32_t af[4];
                ldmx4(af, sbase + SM_A + ao);
#pragma unroll
                for (int fn = 0; fn < 8; fn++)
                    mma_f16(acc[fm][fn], af, bf[fn * 2], bf[fn * 2 + 1]);
            }
        }
    }

    // ---------------- epilogue ----------------
#pragma unroll
    for (int fm = 0; fm < 2; fm++) {
#pragma unroll
        for (int fn = 0; fn < 8; fn++) {
            int col = warp_n * 64 + fn * 8 + (lane & 3) * 2;
            float bv0 = sbias[col], bv1 = sbias[col + 1];
#pragma unroll
            for (int h = 0; h < 2; h++) {
                int row = warp_m * 32 + fm * 16 + (lane >> 2) + h * 8;
                if (m0 + row >= cnt) continue;
                size_t crow = arow0 + row;
                float v0 = acc[fm][fn][h * 2 + 0] + bv0;
                float v1 = acc[fm][fn][h * 2 + 1] + bv1;
                if (PHASE == 1) {
                    v0 = fmaxf(v0, 0.f); v1 = fmaxf(v1, 0.f);
                    __half h0 = __float2half(v0);
                    __half h1 = __float2half(v1);
                    union { unsigned short u[2]; uint32_t w; } pk;
                    pk.u[0] = *(unsigned short*)&h0; pk.u[1] = *(unsigned short*)&h1;
                    *(uint32_t*)(g_h + crow * (size_t)ND + n0 + col) = pk.w;
                } else {
                    float2 v; v.x = v0; v.y = v1;
                    *(float2*)(g_O + crow * (size_t)ND + n0 + col) = v;
                }
            }
        }
    }
}

// ---------------------------------------------------------------- combine
__global__ void combine_kernel(float* __restrict__ out) {
    int t = blockIdx.x;
    int e0 = g_tok_e[2 * t], e1 = g_tok_e[2 * t + 1];
    int r0 = g_offset[e0] + g_tok_pos[2 * t];
    int r1 = g_offset[e1] + g_tok_pos[2 * t + 1];
    float w0 = g_tok_w[2 * t], w1 = g_tok_w[2 * t + 1];
    const float4* a = (const float4*)(g_O + (size_t)r0 * DOUT);
    const float4* b = (const float4*)(g_O + (size_t)r1 * DOUT);
    float4* o = (float4*)(out + (size_t)t * DOUT);
    for (int i = threadIdx.x; i < DOUT / 4; i += blockDim.x) {
        float4 av = a[i], bv = b[i];
        float4 r;
        r.x = w0 * av.x + w1 * bv.x;
        r.y = w0 * av.y + w1 * bv.y;
        r.z = w0 * av.z + w1 * bv.z;
        r.w = w0 * av.w + w1 * bv.w;
        o[i] = r;
    }
}

// ---------------------------------------------------------------- launch
extern "C" void kernel_launch(void* const* d_in, const int* in_sizes, int n_in,
                              void* d_out, int out_size) {
    const float* x       = (const float*)d_in[0];
    const float* noise   = (const float*)d_in[1];
    const float* gate_w  = (const float*)d_in[2];
    const float* gate_b  = (const float*)d_in[3];
    const float* noise_w = (const float*)d_in[4];
    const float* noise_b = (const float*)d_in[5];
    const float* w1      = (const float*)d_in[6];
    const float* b1      = (const float*)d_in[7];
    const float* w2      = (const float*)d_in[8];
    const float* b2      = (const float*)d_in[9];
    float* out = (float*)d_out;

    float* w_out;
    if (out_size >= T * DOUT + T * NE) {
        w_out = out + (size_t)T * DOUT;
    } else {
        cudaGetSymbolAddress((void**)&w_out, g_wdummy);
    }

    cudaFuncSetAttribute(gemm_mma_kernel<1>, cudaFuncAttributeMaxDynamicSharedMemorySize, SMEM_TOT);
    cudaFuncSetAttribute(gemm_mma_kernel<2>, cudaFuncAttributeMaxDynamicSharedMemorySize, SMEM_TOT);

    __half *xh, *w1h, *w2h;
    cudaGetSymbolAddress((void**)&xh, g_xh);
    cudaGetSymbolAddress((void**)&w1h, g_w1);
    cudaGetSymbolAddress((void**)&w2h, g_w2);

    zero_counts_kernel<<<1, 32>>>();
    conv_kernel<<<(T * DIN / 8 + 255) / 256, 256>>>(x, xh, T * DIN / 8);
    conv_kernel<<<(NE * DIN * HID / 8 + 255) / 256, 256>>>(w1, w1h, NE * DIN * HID / 8);
    conv_kernel<<<(NE * HID * DOUT / 8 + 255) / 256, 256>>>(w2, w2h, NE * HID * DOUT / 8);
    gating_kernel<<<T / 16, 512>>>(x, noise, gate_w, gate_b, noise_w, noise_b, w_out);
    offsets_kernel<<<1, 32>>>();
    gemm_mma_kernel<1><<<dim3(NE * (HID / BN), MT), NTHR, SMEM_TOT>>>(b1);
    gemm_mma_kernel<2><<<dim3(NE * (DOUT / BN), MT), NTHR, SMEM_TOT>>>(b2);
    combine_kernel<<<T, 256>>>(out);
}